// round 12
// baseline (speedup 1.0000x reference)
#include <cuda_runtime.h>
#include <cuda_fp16.h>
#include <math.h>

// ---------------------------------------------------------------------------
// GAT 2-layer: N=50000 nodes, E=800000 edges (+N self loops), F=128.
// Layer1: heads=4, out_ch=32.  Layer2: heads=1, out_ch=128.
// CSR-by-dst built once (on a side stream, overlapped with gemm1+alpha1);
// SINGLE-PASS warp softmax-aggregation; fp16 gather mirror; tf32 GEMM.
// ---------------------------------------------------------------------------

#define NMAX   50048
#define ETMAX  (800000 + NMAX)

__device__ float  g_h[(size_t)NMAX * 128];
__device__ __half g_hh[(size_t)NMAX * 128];   // fp16 mirror for gather
__device__ float  g_agg[(size_t)NMAX * 128];
__device__ float  g_aS[NMAX * 4];
__device__ float  g_aD[NMAX * 4];
__device__ int    g_deg[NMAX];
__device__ int    g_rowptr[NMAX + 1];
__device__ int    g_pos[NMAX];
__device__ int    g_colsrc[ETMAX];
__device__ int    g_bsum[64];
__device__ int    g_is64;

// ---------------------------------------------------------------------------
__device__ __forceinline__ int loadIdx(const void* ei, long long pos) {
    if (g_is64) return (int)((const long long*)ei)[pos];
    return ((const int*)ei)[pos];
}

__global__ void detect_kernel(const int* ei) {
    int lane = threadIdx.x;
    int hi = ei[2 * lane + 1];
    unsigned z = __ballot_sync(0xffffffffu, hi == 0);
    if (lane == 0) g_is64 = (__popc(z) >= 30) ? 1 : 0;
}

__global__ void zero_int(int* p, int count) {
    int i = blockIdx.x * blockDim.x + threadIdx.x;
    if (i < count) p[i] = 0;
}

__global__ void hist_kernel(const void* __restrict__ ei, int E, int n, int* deg) {
    int et = blockIdx.x * blockDim.x + threadIdx.x;
    int ET = E + n;
    if (et >= ET) return;
    int d = (et < E) ? loadIdx(ei, (long long)E + et) : et - E;
    atomicAdd(&deg[d], 1);
}

// ---- 3-phase scan --------------------------------------------------------
__global__ void block_sum_kernel(const int* __restrict__ deg, int* bsum, int n) {
    __shared__ int wsum[8];
    int t = threadIdx.x, lane = t & 31, w = t >> 5;
    int base = blockIdx.x * 1024 + t * 4;
    int v = 0;
#pragma unroll
    for (int i = 0; i < 4; i++)
        if (base + i < n) v += deg[base + i];
#pragma unroll
    for (int o = 16; o; o >>= 1) v += __shfl_xor_sync(0xffffffffu, v, o);
    if (lane == 0) wsum[w] = v;
    __syncthreads();
    if (t == 0) {
        int s = 0;
#pragma unroll
        for (int i = 0; i < 8; i++) s += wsum[i];
        bsum[blockIdx.x] = s;
    }
}

__global__ void scan_bsum_kernel(int* bsum, int nb) {
    int lane = threadIdx.x;
    int carry = 0;
    for (int base = 0; base < nb; base += 32) {
        int i = base + lane;
        int v = (i < nb) ? bsum[i] : 0;
        int incl = v;
#pragma unroll
        for (int o = 1; o < 32; o <<= 1) {
            int x = __shfl_up_sync(0xffffffffu, incl, o);
            if (lane >= o) incl += x;
        }
        if (i < nb) bsum[i] = carry + incl - v;
        carry += __shfl_sync(0xffffffffu, incl, 31);
    }
}

__global__ void scan_final_kernel(const int* __restrict__ deg,
                                  const int* __restrict__ bsum,
                                  int* rowptr, int* pos, int n) {
    __shared__ int wsum[8];
    int t = threadIdx.x, lane = t & 31, w = t >> 5;
    int base = blockIdx.x * 1024 + t * 4;
    int v[4], p[4];
    int run = 0;
#pragma unroll
    for (int i = 0; i < 4; i++) {
        v[i] = (base + i < n) ? deg[base + i] : 0;
        run += v[i];
        p[i] = run;
    }
    int incl = run;
#pragma unroll
    for (int o = 1; o < 32; o <<= 1) {
        int x = __shfl_up_sync(0xffffffffu, incl, o);
        if (lane >= o) incl += x;
    }
    int wexcl = incl - run;
    if (lane == 31) wsum[w] = incl;
    __syncthreads();
    if (t == 0) {
        int a = 0;
#pragma unroll
        for (int i = 0; i < 8; i++) { int x = wsum[i]; wsum[i] = a; a += x; }
    }
    __syncthreads();
    int off = bsum[blockIdx.x] + wsum[w] + wexcl;
#pragma unroll
    for (int i = 0; i < 4; i++) {
        int idx = base + i;
        if (idx < n) {
            rowptr[idx + 1] = off + p[i];
            pos[idx]        = off + p[i] - v[i];
        }
    }
    if (blockIdx.x == 0 && t == 0) rowptr[0] = 0;
}

__global__ void scatter_kernel(const void* __restrict__ ei, int E, int n,
                               int* pos, int* colsrc) {
    int et = blockIdx.x * blockDim.x + threadIdx.x;
    int ET = E + n;
    if (et >= ET) return;
    int s, d;
    if (et < E) { s = loadIdx(ei, et); d = loadIdx(ei, (long long)E + et); }
    else        { s = d = et - E; }
    int p = atomicAdd(&pos[d], 1);
    colsrc[p] = s;
}

// ---------------------------------------------------------------------------
// tf32 tensor-core GEMM: C[M,128] = op(A)[M,128] @ W[128,128]
// ---------------------------------------------------------------------------
__device__ __forceinline__ unsigned f2tf(float x) {
    unsigned r;
    asm("cvt.rna.tf32.f32 %0, %1;" : "=r"(r) : "f"(x));
    return r;
}

__device__ __forceinline__ void mma_tf32(float* c, const unsigned* a,
                                         unsigned b0, unsigned b1) {
    asm volatile(
        "mma.sync.aligned.m16n8k8.row.col.f32.tf32.tf32.f32 "
        "{%0,%1,%2,%3}, {%4,%5,%6,%7}, {%8,%9}, {%0,%1,%2,%3};"
        : "+f"(c[0]), "+f"(c[1]), "+f"(c[2]), "+f"(c[3])
        : "r"(a[0]), "r"(a[1]), "r"(a[2]), "r"(a[3]), "r"(b0), "r"(b1));
}

template <bool RELU_BIAS>
__global__ void gemm128_tc(const float* __restrict__ A, const float* __restrict__ W,
                           const float* __restrict__ bias, float* __restrict__ C, int M)
{
    __shared__ unsigned As[128][36];
    __shared__ unsigned Bs[32][136];

    int t = threadIdx.x, lane = t & 31, wid = t >> 5;
    int wm = wid & 3, wn = wid >> 2;
    int rowBase = blockIdx.x * 128;

    float acc[2][8][4];
#pragma unroll
    for (int mt = 0; mt < 2; mt++)
#pragma unroll
        for (int nt = 0; nt < 8; nt++)
#pragma unroll
            for (int i = 0; i < 4; i++) acc[mt][nt][i] = 0.f;

    for (int k0 = 0; k0 < 128; k0 += 32) {
#pragma unroll
        for (int r = 0; r < 4; r++) {
            int id = t + r * 256;
            int arow = id >> 3;
            int cg   = (id & 7) * 4;
            int grow = rowBase + arow;
            float4 v = make_float4(0.f, 0.f, 0.f, 0.f);
            if (grow < M)
                v = *(const float4*)(A + (size_t)grow * 128 + k0 + cg);
            if (RELU_BIAS) {
                const float* bb = bias + k0 + cg;
                v.x = fmaxf(v.x + bb[0], 0.f);
                v.y = fmaxf(v.y + bb[1], 0.f);
                v.z = fmaxf(v.z + bb[2], 0.f);
                v.w = fmaxf(v.w + bb[3], 0.f);
            }
            As[arow][cg + 0] = f2tf(v.x);
            As[arow][cg + 1] = f2tf(v.y);
            As[arow][cg + 2] = f2tf(v.z);
            As[arow][cg + 3] = f2tf(v.w);
        }
#pragma unroll
        for (int r = 0; r < 4; r++) {
            int id = t + r * 256;
            int krow = id >> 5;
            int c4   = (id & 31) * 4;
            float4 w = *(const float4*)(W + (size_t)(k0 + krow) * 128 + c4);
            Bs[krow][c4 + 0] = f2tf(w.x);
            Bs[krow][c4 + 1] = f2tf(w.y);
            Bs[krow][c4 + 2] = f2tf(w.z);
            Bs[krow][c4 + 3] = f2tf(w.w);
        }
        __syncthreads();

#pragma unroll
        for (int ks = 0; ks < 4; ks++) {
            int kk = ks * 8;
            unsigned a[2][4];
#pragma unroll
            for (int mt = 0; mt < 2; mt++) {
                int row = wm * 32 + mt * 16 + (lane >> 2);
                int kc  = kk + (lane & 3);
                a[mt][0] = As[row][kc];
                a[mt][1] = As[row + 8][kc];
                a[mt][2] = As[row][kc + 4];
                a[mt][3] = As[row + 8][kc + 4];
            }
#pragma unroll
            for (int nt = 0; nt < 8; nt++) {
                int col = wn * 64 + nt * 8 + (lane >> 2);
                int kc  = kk + (lane & 3);
                unsigned b0 = Bs[kc][col];
                unsigned b1 = Bs[kc + 4][col];
                mma_tf32(acc[0][nt], a[0], b0, b1);
                mma_tf32(acc[1][nt], a[1], b0, b1);
            }
        }
        __syncthreads();
    }

#pragma unroll
    for (int mt = 0; mt < 2; mt++) {
#pragma unroll
        for (int nt = 0; nt < 8; nt++) {
            int row = rowBase + wm * 32 + mt * 16 + (lane >> 2);
            int col = wn * 64 + nt * 8 + (lane & 3) * 2;
            if (row < M)
                *(float2*)(C + (size_t)row * 128 + col) =
                    make_float2(acc[mt][nt][0], acc[mt][nt][1]);
            if (row + 8 < M)
                *(float2*)(C + (size_t)(row + 8) * 128 + col) =
                    make_float2(acc[mt][nt][2], acc[mt][nt][3]);
        }
    }
}

// ---------------------------------------------------------------------------
// alpha_src / alpha_dst + fp16 mirror emission (fully coalesced)
// ---------------------------------------------------------------------------
template <int H>
__global__ void alpha_kernel(const float* __restrict__ h,
                             const float* __restrict__ attS,
                             const float* __restrict__ attD,
                             float* __restrict__ aS, float* __restrict__ aD,
                             __half* __restrict__ hh, int n)
{
    int w    = (int)((blockIdx.x * (size_t)blockDim.x + threadIdx.x) >> 5);
    int lane = threadIdx.x & 31;
    if (w >= n) return;
    float4 v = *(const float4*)(h + (size_t)w * 128 + lane * 4);

    __half2 p0 = __floats2half2_rn(v.x, v.y);
    __half2 p1 = __floats2half2_rn(v.z, v.w);
    uint2 u = make_uint2(*(unsigned*)&p0, *(unsigned*)&p1);
    *(uint2*)(hh + (size_t)w * 128 + lane * 4) = u;

    float4 s = *(const float4*)(attS + lane * 4);
    float4 d = *(const float4*)(attD + lane * 4);
    float ps = v.x * s.x + v.y * s.y + v.z * s.z + v.w * s.w;
    float pd = v.x * d.x + v.y * d.y + v.z * d.z + v.w * d.w;
    const int LPH = 32 / H;
#pragma unroll
    for (int o = LPH >> 1; o; o >>= 1) {
        ps += __shfl_xor_sync(0xffffffffu, ps, o);
        pd += __shfl_xor_sync(0xffffffffu, pd, o);
    }
    if ((lane & (LPH - 1)) == 0) {
        int hd = lane / LPH;
        aS[(size_t)w * H + hd] = ps;
        aD[(size_t)w * H + hd] = pd;
    }
}

// ---------------------------------------------------------------------------
// SINGLE-PASS warp-per-node softmax aggregation (no max shift, logits
// bounded; denom accumulates per-lane since every lane visits every edge).
// ---------------------------------------------------------------------------
template <int H, bool ADD_BIAS>
__global__ void node_agg_kernel(const int* __restrict__ rowptr,
                                const int* __restrict__ colsrc,
                                const float* __restrict__ aS,
                                const float* __restrict__ aD,
                                const __half* __restrict__ hh,
                                const float* __restrict__ bias,
                                float* __restrict__ out, int n)
{
    int d    = (int)((blockIdx.x * (size_t)blockDim.x + threadIdx.x) >> 5);
    int lane = threadIdx.x & 31;
    if (d >= n) return;
    int beg = rowptr[d], end = rowptr[d + 1];

    const int OC = 128 / H;
    int hd = (lane * 4) / OC;
    float aDh = aD[(size_t)d * H + hd];

    float den = 0.f;
    float4 acc = make_float4(0.f, 0.f, 0.f, 0.f);
    for (int base = beg; base < end; base += 32) {
        int cnt = min(32, end - base);
        int idx = base + lane;
        int sv  = (idx < end) ? colsrc[idx] : 0;
#pragma unroll 4
        for (int j = 0; j < cnt; j++) {
            int sidx = __shfl_sync(0xffffffffu, sv, j);
            float e = aS[(size_t)sidx * H + hd] + aDh;
            e = e > 0.f ? e : 0.2f * e;
            float wgt = __expf(e);
            den += wgt;
            uint2 u = *(const uint2*)(hh + (size_t)sidx * 128 + lane * 4);
            float2 v0 = __half22float2(*(__half2*)&u.x);
            float2 v1 = __half22float2(*(__half2*)&u.y);
            acc.x += wgt * v0.x;
            acc.y += wgt * v0.y;
            acc.z += wgt * v1.x;
            acc.w += wgt * v1.y;
        }
    }
    float inv = 1.f / fmaxf(den, 1e-38f);
    acc.x *= inv; acc.y *= inv; acc.z *= inv; acc.w *= inv;
    if (ADD_BIAS) {
        float4 b = *(const float4*)(bias + lane * 4);
        acc.x += b.x; acc.y += b.y; acc.z += b.z; acc.w += b.w;
    }
    *(float4*)(out + (size_t)d * 128 + lane * 4) = acc;
}

// ---------------------------------------------------------------------------
// host
// ---------------------------------------------------------------------------
extern "C" void kernel_launch(void* const* d_in, const int* in_sizes, int n_in,
                              void* d_out, int out_size)
{
    const float* x   = (const float*)d_in[0];
    const void*  ei  = d_in[1];
    const float* W1  = (const float*)d_in[2];
    const float* as1 = (const float*)d_in[3];
    const float* ad1 = (const float*)d_in[4];
    const float* b1  = (const float*)d_in[5];
    const float* W2  = (const float*)d_in[6];
    const float* as2 = (const float*)d_in[7];
    const float* ad2 = (const float*)d_in[8];
    const float* b2  = (const float*)d_in[9];
    float* out = (float*)d_out;

    int n  = in_sizes[0] / 128;
    int E  = in_sizes[1] / 2;
    int ET = E + n;

    float *h, *agg, *aS, *aD;
    __half *hh;
    int *deg, *rowptr, *pos, *colsrc, *bsum;
    cudaGetSymbolAddress((void**)&h,      g_h);
    cudaGetSymbolAddress((void**)&hh,     g_hh);
    cudaGetSymbolAddress((void**)&agg,    g_agg);
    cudaGetSymbolAddress((void**)&aS,     g_aS);
    cudaGetSymbolAddress((void**)&aD,     g_aD);
    cudaGetSymbolAddress((void**)&deg,    g_deg);
    cudaGetSymbolAddress((void**)&rowptr, g_rowptr);
    cudaGetSymbolAddress((void**)&pos,    g_pos);
    cudaGetSymbolAddress((void**)&colsrc, g_colsrc);
    cudaGetSymbolAddress((void**)&bsum,   g_bsum);

    // lazily created side stream + fork/join events (host objects only)
    static cudaStream_t s2 = nullptr;
    static cudaEvent_t evFork = nullptr, evJoin = nullptr;
    if (s2 == nullptr) {
        cudaStreamCreateWithFlags(&s2, cudaStreamNonBlocking);
        cudaEventCreateWithFlags(&evFork, cudaEventDisableTiming);
        cudaEventCreateWithFlags(&evJoin, cudaEventDisableTiming);
    }

    const int TB = 256;
    int gridGemm  = (n + 127) / 128;
    int gridEdge  = (ET + TB - 1) / TB;
    int gridNodeW = (n + 7) / 8;
    int nScanBlk  = (n + 1023) / 1024;

    // detect first (CSR branch depends on g_is64)
    detect_kernel<<<1, 32>>>((const int*)ei);

    // ---- fork: CSR build on s2, gemm1+alpha1 on main stream ----
    cudaEventRecord(evFork, 0);
    cudaStreamWaitEvent(s2, evFork, 0);

    zero_int<<<(n + TB - 1) / TB, TB, 0, s2>>>(deg, n);
    hist_kernel<<<gridEdge, TB, 0, s2>>>(ei, E, n, deg);
    block_sum_kernel<<<nScanBlk, 256, 0, s2>>>(deg, bsum, n);
    scan_bsum_kernel<<<1, 32, 0, s2>>>(bsum, nScanBlk);
    scan_final_kernel<<<nScanBlk, 256, 0, s2>>>(deg, bsum, rowptr, pos, n);
    scatter_kernel<<<gridEdge, TB, 0, s2>>>(ei, E, n, pos, colsrc);
    cudaEventRecord(evJoin, s2);

    gemm128_tc<false><<<gridGemm, TB>>>(x, W1, nullptr, h, n);
    alpha_kernel<4><<<gridNodeW, TB>>>(h, as1, ad1, aS, aD, hh, n);

    // ---- join ----
    cudaStreamWaitEvent(0, evJoin, 0);

    // ----- layer 1 aggregation (H=4) -----
    node_agg_kernel<4, false><<<gridNodeW, TB>>>(rowptr, colsrc, aS, aD, hh,
                                                 nullptr, agg, n);

    // ----- layer 2 (H=1) -----
    gemm128_tc<true><<<gridGemm, TB>>>(agg, W2, b1, h, n);
    alpha_kernel<1><<<gridNodeW, TB>>>(h, as2, ad2, aS, aD, hh, n);
    node_agg_kernel<1, true><<<gridNodeW, TB>>>(rowptr, colsrc, aS, aD, hh,
                                                b2, out, n);
}

// round 14
// speedup vs baseline: 1.4014x; 1.4014x over previous
#include <cuda_runtime.h>
#include <cuda_fp16.h>
#include <math.h>

// ---------------------------------------------------------------------------
// GAT 2-layer: N=50000 nodes, E=800000 edges (+N self loops), F=128.
// Layer1: heads=4, out_ch=32.  Layer2: heads=1, out_ch=128.
// CSR-by-dst built once; SINGLE-PASS warp softmax-aggregation (bias/relu
// fused into agg epilogue); fp16 gather mirror; cp.async double-buffered
// tf32 tensor GEMM with cvt.rna.tf32 on register loads (RN numerics).
// ---------------------------------------------------------------------------

#define NMAX   50048
#define ETMAX  (800000 + NMAX)

__device__ float  g_h[(size_t)NMAX * 128];
__device__ __half g_hh[(size_t)NMAX * 128];   // fp16 mirror for gather
__device__ float  g_agg[(size_t)NMAX * 128];
__device__ float  g_aS[NMAX * 4];
__device__ float  g_aD[NMAX * 4];
__device__ int    g_deg[NMAX];
__device__ int    g_rowptr[NMAX + 1];
__device__ int    g_pos[NMAX];
__device__ int    g_colsrc[ETMAX];
__device__ int    g_bsum[64];
__device__ int    g_is64;

// ---------------------------------------------------------------------------
__device__ __forceinline__ int loadIdx(const void* ei, long long pos) {
    if (g_is64) return (int)((const long long*)ei)[pos];
    return ((const int*)ei)[pos];
}

__global__ void detect_kernel(const int* ei) {
    int lane = threadIdx.x;
    int hi = ei[2 * lane + 1];
    unsigned z = __ballot_sync(0xffffffffu, hi == 0);
    if (lane == 0) g_is64 = (__popc(z) >= 30) ? 1 : 0;
}

__global__ void zero_int(int* p, int count) {
    int i = blockIdx.x * blockDim.x + threadIdx.x;
    if (i < count) p[i] = 0;
}

__global__ void hist_kernel(const void* __restrict__ ei, int E, int n, int* deg) {
    int et = blockIdx.x * blockDim.x + threadIdx.x;
    int ET = E + n;
    if (et >= ET) return;
    int d = (et < E) ? loadIdx(ei, (long long)E + et) : et - E;
    atomicAdd(&deg[d], 1);
}

// ---- 3-phase scan --------------------------------------------------------
__global__ void block_sum_kernel(const int* __restrict__ deg, int* bsum, int n) {
    __shared__ int wsum[8];
    int t = threadIdx.x, lane = t & 31, w = t >> 5;
    int base = blockIdx.x * 1024 + t * 4;
    int v = 0;
#pragma unroll
    for (int i = 0; i < 4; i++)
        if (base + i < n) v += deg[base + i];
#pragma unroll
    for (int o = 16; o; o >>= 1) v += __shfl_xor_sync(0xffffffffu, v, o);
    if (lane == 0) wsum[w] = v;
    __syncthreads();
    if (t == 0) {
        int s = 0;
#pragma unroll
        for (int i = 0; i < 8; i++) s += wsum[i];
        bsum[blockIdx.x] = s;
    }
}

__global__ void scan_bsum_kernel(int* bsum, int nb) {
    int lane = threadIdx.x;
    int carry = 0;
    for (int base = 0; base < nb; base += 32) {
        int i = base + lane;
        int v = (i < nb) ? bsum[i] : 0;
        int incl = v;
#pragma unroll
        for (int o = 1; o < 32; o <<= 1) {
            int x = __shfl_up_sync(0xffffffffu, incl, o);
            if (lane >= o) incl += x;
        }
        if (i < nb) bsum[i] = carry + incl - v;
        carry += __shfl_sync(0xffffffffu, incl, 31);
    }
}

__global__ void scan_final_kernel(const int* __restrict__ deg,
                                  const int* __restrict__ bsum,
                                  int* rowptr, int* pos, int n) {
    __shared__ int wsum[8];
    int t = threadIdx.x, lane = t & 31, w = t >> 5;
    int base = blockIdx.x * 1024 + t * 4;
    int v[4], p[4];
    int run = 0;
#pragma unroll
    for (int i = 0; i < 4; i++) {
        v[i] = (base + i < n) ? deg[base + i] : 0;
        run += v[i];
        p[i] = run;
    }
    int incl = run;
#pragma unroll
    for (int o = 1; o < 32; o <<= 1) {
        int x = __shfl_up_sync(0xffffffffu, incl, o);
        if (lane >= o) incl += x;
    }
    int wexcl = incl - run;
    if (lane == 31) wsum[w] = incl;
    __syncthreads();
    if (t == 0) {
        int a = 0;
#pragma unroll
        for (int i = 0; i < 8; i++) { int x = wsum[i]; wsum[i] = a; a += x; }
    }
    __syncthreads();
    int off = bsum[blockIdx.x] + wsum[w] + wexcl;
#pragma unroll
    for (int i = 0; i < 4; i++) {
        int idx = base + i;
        if (idx < n) {
            rowptr[idx + 1] = off + p[i];
            pos[idx]        = off + p[i] - v[i];
        }
    }
    if (blockIdx.x == 0 && t == 0) rowptr[0] = 0;
}

__global__ void scatter_kernel(const void* __restrict__ ei, int E, int n,
                               int* pos, int* colsrc) {
    int et = blockIdx.x * blockDim.x + threadIdx.x;
    int ET = E + n;
    if (et >= ET) return;
    int s, d;
    if (et < E) { s = loadIdx(ei, et); d = loadIdx(ei, (long long)E + et); }
    else        { s = d = et - E; }
    int p = atomicAdd(&pos[d], 1);
    colsrc[p] = s;
}

// ---------------------------------------------------------------------------
// cp.async double-buffered tf32 GEMM: C[M,128] = A[M,128] @ W[128,128]
// smem holds fp32; cvt.rna.tf32 applied on register loads (RN rounding).
// ---------------------------------------------------------------------------
#define CP_ASYNC16(dst_smem_u32, src_ptr) \
    asm volatile("cp.async.ca.shared.global [%0], [%1], 16;\n" \
                 :: "r"(dst_smem_u32), "l"(src_ptr))
#define CP_COMMIT() asm volatile("cp.async.commit_group;\n")
#define CP_WAIT(N)  asm volatile("cp.async.wait_group %0;\n" :: "n"(N))

__device__ __forceinline__ unsigned f2tf(float x) {
    unsigned r;
    asm("cvt.rna.tf32.f32 %0, %1;" : "=r"(r) : "f"(x));
    return r;
}

__device__ __forceinline__ void mma_tf32(float* c, const unsigned* a,
                                         unsigned b0, unsigned b1) {
    asm volatile(
        "mma.sync.aligned.m16n8k8.row.col.f32.tf32.tf32.f32 "
        "{%0,%1,%2,%3}, {%4,%5,%6,%7}, {%8,%9}, {%0,%1,%2,%3};"
        : "+f"(c[0]), "+f"(c[1]), "+f"(c[2]), "+f"(c[3])
        : "r"(a[0]), "r"(a[1]), "r"(a[2]), "r"(a[3]), "r"(b0), "r"(b1));
}

#define AS_STRIDE 36
#define BS_STRIDE 136
#define AS_ELEMS  (128 * AS_STRIDE)          // per buffer
#define BS_ELEMS  (32 * BS_STRIDE)
#define GEMM_SMEM ((2 * AS_ELEMS + 2 * BS_ELEMS) * 4)

__global__ void gemm128_cp(const float* __restrict__ A, const float* __restrict__ W,
                           float* __restrict__ C, int M)
{
    extern __shared__ float dsm[];
    float* AsBase = dsm;                      // [2][128][36]
    float* BsBase = dsm + 2 * AS_ELEMS;       // [2][32][136]

    int t = threadIdx.x, lane = t & 31, wid = t >> 5;
    int wm = wid & 3, wn = wid >> 2;
    int rowBase = blockIdx.x * 128;

    float acc[2][8][4];
#pragma unroll
    for (int mt = 0; mt < 2; mt++)
#pragma unroll
        for (int nt = 0; nt < 8; nt++)
#pragma unroll
            for (int i = 0; i < 4; i++) acc[mt][nt][i] = 0.f;

    auto loadChunk = [&](int k0, int buf) {
        float* As = AsBase + buf * AS_ELEMS;
        float* Bs = BsBase + buf * BS_ELEMS;
#pragma unroll
        for (int r = 0; r < 4; r++) {
            int id = t + r * 256;
            int arow = id >> 3;
            int cg   = (id & 7) * 4;
            int grow = rowBase + arow;
            float* dst = As + arow * AS_STRIDE + cg;
            if (grow < M) {
                unsigned sdst = (unsigned)__cvta_generic_to_shared(dst);
                CP_ASYNC16(sdst, A + (size_t)grow * 128 + k0 + cg);
            } else {
                *(float4*)dst = make_float4(0.f, 0.f, 0.f, 0.f);
            }
        }
#pragma unroll
        for (int r = 0; r < 4; r++) {
            int id = t + r * 256;
            int krow = id >> 5;
            int c4   = (id & 31) * 4;
            float* dst = Bs + krow * BS_STRIDE + c4;
            unsigned sdst = (unsigned)__cvta_generic_to_shared(dst);
            CP_ASYNC16(sdst, W + (size_t)(k0 + krow) * 128 + c4);
        }
        CP_COMMIT();
    };

    auto compute = [&](int buf) {
        const float* As = AsBase + buf * AS_ELEMS;
        const float* Bs = BsBase + buf * BS_ELEMS;
#pragma unroll
        for (int ks = 0; ks < 4; ks++) {
            int kk = ks * 8;
            unsigned a[2][4];
#pragma unroll
            for (int mt = 0; mt < 2; mt++) {
                int row = wm * 32 + mt * 16 + (lane >> 2);
                int kc  = kk + (lane & 3);
                a[mt][0] = f2tf(As[row * AS_STRIDE + kc]);
                a[mt][1] = f2tf(As[(row + 8) * AS_STRIDE + kc]);
                a[mt][2] = f2tf(As[row * AS_STRIDE + kc + 4]);
                a[mt][3] = f2tf(As[(row + 8) * AS_STRIDE + kc + 4]);
            }
#pragma unroll
            for (int nt = 0; nt < 8; nt++) {
                int col = wn * 64 + nt * 8 + (lane >> 2);
                int kc  = kk + (lane & 3);
                unsigned b0 = f2tf(Bs[kc * BS_STRIDE + col]);
                unsigned b1 = f2tf(Bs[(kc + 4) * BS_STRIDE + col]);
                mma_tf32(acc[0][nt], a[0], b0, b1);
                mma_tf32(acc[1][nt], a[1], b0, b1);
            }
        }
    };

    // ---- pipelined mainloop: chunks k0 = 0,32,64,96 ----
    loadChunk(0, 0);
    loadChunk(32, 1);
    CP_WAIT(1);
    __syncthreads();
    compute(0);
    __syncthreads();
    loadChunk(64, 0);
    CP_WAIT(1);
    __syncthreads();
    compute(1);
    __syncthreads();
    loadChunk(96, 1);
    CP_WAIT(1);
    __syncthreads();
    compute(0);
    __syncthreads();
    CP_WAIT(0);
    __syncthreads();
    compute(1);

    // ---- epilogue ----
#pragma unroll
    for (int mt = 0; mt < 2; mt++) {
#pragma unroll
        for (int nt = 0; nt < 8; nt++) {
            int row = rowBase + wm * 32 + mt * 16 + (lane >> 2);
            int col = wn * 64 + nt * 8 + (lane & 3) * 2;
            if (row < M)
                *(float2*)(C + (size_t)row * 128 + col) =
                    make_float2(acc[mt][nt][0], acc[mt][nt][1]);
            if (row + 8 < M)
                *(float2*)(C + (size_t)(row + 8) * 128 + col) =
                    make_float2(acc[mt][nt][2], acc[mt][nt][3]);
        }
    }
}

// ---------------------------------------------------------------------------
// alpha_src / alpha_dst + fp16 mirror emission (fully coalesced)
// ---------------------------------------------------------------------------
template <int H>
__global__ void alpha_kernel(const float* __restrict__ h,
                             const float* __restrict__ attS,
                             const float* __restrict__ attD,
                             float* __restrict__ aS, float* __restrict__ aD,
                             __half* __restrict__ hh, int n)
{
    int w    = (int)((blockIdx.x * (size_t)blockDim.x + threadIdx.x) >> 5);
    int lane = threadIdx.x & 31;
    if (w >= n) return;
    float4 v = *(const float4*)(h + (size_t)w * 128 + lane * 4);

    __half2 p0 = __floats2half2_rn(v.x, v.y);
    __half2 p1 = __floats2half2_rn(v.z, v.w);
    uint2 u = make_uint2(*(unsigned*)&p0, *(unsigned*)&p1);
    *(uint2*)(hh + (size_t)w * 128 + lane * 4) = u;

    float4 s = *(const float4*)(attS + lane * 4);
    float4 d = *(const float4*)(attD + lane * 4);
    float ps = v.x * s.x + v.y * s.y + v.z * s.z + v.w * s.w;
    float pd = v.x * d.x + v.y * d.y + v.z * d.z + v.w * d.w;
    const int LPH = 32 / H;
#pragma unroll
    for (int o = LPH >> 1; o; o >>= 1) {
        ps += __shfl_xor_sync(0xffffffffu, ps, o);
        pd += __shfl_xor_sync(0xffffffffu, pd, o);
    }
    if ((lane & (LPH - 1)) == 0) {
        int hd = lane / LPH;
        aS[(size_t)w * H + hd] = ps;
        aD[(size_t)w * H + hd] = pd;
    }
}

// ---------------------------------------------------------------------------
// SINGLE-PASS warp-per-node softmax aggregation.
// RELU=true : out = relu(acc/den + bias)  (layer1, feeds gemm2)
// RELU=false: out = acc/den + bias        (layer2 final)
// ---------------------------------------------------------------------------
template <int H, bool RELU>
__global__ void node_agg_kernel(const int* __restrict__ rowptr,
                                const int* __restrict__ colsrc,
                                const float* __restrict__ aS,
                                const float* __restrict__ aD,
                                const __half* __restrict__ hh,
                                const float* __restrict__ bias,
                                float* __restrict__ out, int n)
{
    int d    = (int)((blockIdx.x * (size_t)blockDim.x + threadIdx.x) >> 5);
    int lane = threadIdx.x & 31;
    if (d >= n) return;
    int beg = rowptr[d], end = rowptr[d + 1];

    const int OC = 128 / H;
    int hd = (lane * 4) / OC;
    float aDh = aD[(size_t)d * H + hd];

    float den = 0.f;
    float4 acc = make_float4(0.f, 0.f, 0.f, 0.f);
    for (int base = beg; base < end; base += 32) {
        int cnt = min(32, end - base);
        int idx = base + lane;
        int sv  = (idx < end) ? colsrc[idx] : 0;
#pragma unroll 4
        for (int j = 0; j < cnt; j++) {
            int sidx = __shfl_sync(0xffffffffu, sv, j);
            float e = aS[(size_t)sidx * H + hd] + aDh;
            e = e > 0.f ? e : 0.2f * e;
            float wgt = __expf(e);
            den += wgt;
            uint2 u = *(const uint2*)(hh + (size_t)sidx * 128 + lane * 4);
            float2 v0 = __half22float2(*(__half2*)&u.x);
            float2 v1 = __half22float2(*(__half2*)&u.y);
            acc.x += wgt * v0.x;
            acc.y += wgt * v0.y;
            acc.z += wgt * v1.x;
            acc.w += wgt * v1.y;
        }
    }
    float inv = 1.f / fmaxf(den, 1e-38f);
    float4 b = *(const float4*)(bias + lane * 4);
    acc.x = acc.x * inv + b.x;
    acc.y = acc.y * inv + b.y;
    acc.z = acc.z * inv + b.z;
    acc.w = acc.w * inv + b.w;
    if (RELU) {
        acc.x = fmaxf(acc.x, 0.f);
        acc.y = fmaxf(acc.y, 0.f);
        acc.z = fmaxf(acc.z, 0.f);
        acc.w = fmaxf(acc.w, 0.f);
    }
    *(float4*)(out + (size_t)d * 128 + lane * 4) = acc;
}

// ---------------------------------------------------------------------------
// host
// ---------------------------------------------------------------------------
extern "C" void kernel_launch(void* const* d_in, const int* in_sizes, int n_in,
                              void* d_out, int out_size)
{
    const float* x   = (const float*)d_in[0];
    const void*  ei  = d_in[1];
    const float* W1  = (const float*)d_in[2];
    const float* as1 = (const float*)d_in[3];
    const float* ad1 = (const float*)d_in[4];
    const float* b1  = (const float*)d_in[5];
    const float* W2  = (const float*)d_in[6];
    const float* as2 = (const float*)d_in[7];
    const float* ad2 = (const float*)d_in[8];
    const float* b2  = (const float*)d_in[9];
    float* out = (float*)d_out;

    int n  = in_sizes[0] / 128;
    int E  = in_sizes[1] / 2;
    int ET = E + n;

    float *h, *agg, *aS, *aD;
    __half *hh;
    int *deg, *rowptr, *pos, *colsrc, *bsum;
    cudaGetSymbolAddress((void**)&h,      g_h);
    cudaGetSymbolAddress((void**)&hh,     g_hh);
    cudaGetSymbolAddress((void**)&agg,    g_agg);
    cudaGetSymbolAddress((void**)&aS,     g_aS);
    cudaGetSymbolAddress((void**)&aD,     g_aD);
    cudaGetSymbolAddress((void**)&deg,    g_deg);
    cudaGetSymbolAddress((void**)&rowptr, g_rowptr);
    cudaGetSymbolAddress((void**)&pos,    g_pos);
    cudaGetSymbolAddress((void**)&colsrc, g_colsrc);
    cudaGetSymbolAddress((void**)&bsum,   g_bsum);

    static bool inited = false;
    if (!inited) {
        cudaFuncSetAttribute(gemm128_cp,
                             cudaFuncAttributeMaxDynamicSharedMemorySize,
                             GEMM_SMEM);
        inited = true;
    }

    const int TB = 256;
    int gridGemm  = (n + 127) / 128;
    int gridEdge  = (ET + TB - 1) / TB;
    int gridNodeW = (n + 7) / 8;
    int nScanBlk  = (n + 1023) / 1024;

    // CSR build interleaved with gemm1 (single stream)
    detect_kernel<<<1, 32>>>((const int*)ei);
    zero_int<<<(n + TB - 1) / TB, TB>>>(deg, n);
    hist_kernel<<<gridEdge, TB>>>(ei, E, n, deg);
    gemm128_cp<<<gridGemm, TB, GEMM_SMEM>>>(x, W1, h, n);
    block_sum_kernel<<<nScanBlk, 256>>>(deg, bsum, n);
    scan_bsum_kernel<<<1, 32>>>(bsum, nScanBlk);
    scan_final_kernel<<<nScanBlk, 256>>>(deg, bsum, rowptr, pos, n);
    scatter_kernel<<<gridEdge, TB>>>(ei, E, n, pos, colsrc);

    // ----- layer 1 (H=4): agg applies relu(.+b1) -----
    alpha_kernel<4><<<gridNodeW, TB>>>(h, as1, ad1, aS, aD, hh, n);
    node_agg_kernel<4, true><<<gridNodeW, TB>>>(rowptr, colsrc, aS, aD, hh,
                                                b1, agg, n);

    // ----- layer 2 (H=1): agg applies (.+b2) -----
    gemm128_cp<<<gridGemm, TB, GEMM_SMEM>>>(agg, W2, h, n);
    alpha_kernel<1><<<gridNodeW, TB>>>(h, as2, ad2, aS, aD, hh, n);
    node_agg_kernel<1, false><<<gridNodeW, TB>>>(rowptr, colsrc, aS, aD, hh,
                                                 b2, out, n);
}

// round 15
// speedup vs baseline: 1.4744x; 1.0521x over previous
#include <cuda_runtime.h>
#include <cuda_fp16.h>
#include <math.h>

// ---------------------------------------------------------------------------
// GAT 2-layer: N=50000 nodes, E=800000 edges (+N self loops), F=128.
// Layer1: heads=4, out_ch=32.  Layer2: heads=1, out_ch=128.
// CSR-by-dst built once; SINGLE-PASS warp softmax-aggregation (bias/relu in
// agg epilogue); GEMM with FUSED alpha + fp16-mirror epilogue (no fp32 h).
// ---------------------------------------------------------------------------

#define NMAX   50048
#define ETMAX  (800000 + NMAX)

__device__ __half g_hh[(size_t)NMAX * 128];   // fp16 h (gather source)
__device__ float  g_agg[(size_t)NMAX * 128];
__device__ float  g_aS[NMAX * 4];
__device__ float  g_aD[NMAX * 4];
__device__ int    g_deg[NMAX];
__device__ int    g_rowptr[NMAX + 1];
__device__ int    g_pos[NMAX];
__device__ int    g_colsrc[ETMAX];
__device__ int    g_bsum[64];
__device__ int    g_is64;

// ---------------------------------------------------------------------------
__device__ __forceinline__ int loadIdx(const void* ei, long long pos) {
    if (g_is64) return (int)((const long long*)ei)[pos];
    return ((const int*)ei)[pos];
}

__global__ void detect_kernel(const int* ei) {
    int lane = threadIdx.x;
    int hi = ei[2 * lane + 1];
    unsigned z = __ballot_sync(0xffffffffu, hi == 0);
    if (lane == 0) g_is64 = (__popc(z) >= 30) ? 1 : 0;
}

__global__ void zero_int(int* p, int count) {
    int i = blockIdx.x * blockDim.x + threadIdx.x;
    if (i < count) p[i] = 0;
}

__global__ void hist_kernel(const void* __restrict__ ei, int E, int n, int* deg) {
    int et = blockIdx.x * blockDim.x + threadIdx.x;
    int ET = E + n;
    if (et >= ET) return;
    int d = (et < E) ? loadIdx(ei, (long long)E + et) : et - E;
    atomicAdd(&deg[d], 1);
}

// ---- 3-phase scan --------------------------------------------------------
__global__ void block_sum_kernel(const int* __restrict__ deg, int* bsum, int n) {
    __shared__ int wsum[8];
    int t = threadIdx.x, lane = t & 31, w = t >> 5;
    int base = blockIdx.x * 1024 + t * 4;
    int v = 0;
#pragma unroll
    for (int i = 0; i < 4; i++)
        if (base + i < n) v += deg[base + i];
#pragma unroll
    for (int o = 16; o; o >>= 1) v += __shfl_xor_sync(0xffffffffu, v, o);
    if (lane == 0) wsum[w] = v;
    __syncthreads();
    if (t == 0) {
        int s = 0;
#pragma unroll
        for (int i = 0; i < 8; i++) s += wsum[i];
        bsum[blockIdx.x] = s;
    }
}

__global__ void scan_bsum_kernel(int* bsum, int nb) {
    int lane = threadIdx.x;
    int carry = 0;
    for (int base = 0; base < nb; base += 32) {
        int i = base + lane;
        int v = (i < nb) ? bsum[i] : 0;
        int incl = v;
#pragma unroll
        for (int o = 1; o < 32; o <<= 1) {
            int x = __shfl_up_sync(0xffffffffu, incl, o);
            if (lane >= o) incl += x;
        }
        if (i < nb) bsum[i] = carry + incl - v;
        carry += __shfl_sync(0xffffffffu, incl, 31);
    }
}

__global__ void scan_final_kernel(const int* __restrict__ deg,
                                  const int* __restrict__ bsum,
                                  int* rowptr, int* pos, int n) {
    __shared__ int wsum[8];
    int t = threadIdx.x, lane = t & 31, w = t >> 5;
    int base = blockIdx.x * 1024 + t * 4;
    int v[4], p[4];
    int run = 0;
#pragma unroll
    for (int i = 0; i < 4; i++) {
        v[i] = (base + i < n) ? deg[base + i] : 0;
        run += v[i];
        p[i] = run;
    }
    int incl = run;
#pragma unroll
    for (int o = 1; o < 32; o <<= 1) {
        int x = __shfl_up_sync(0xffffffffu, incl, o);
        if (lane >= o) incl += x;
    }
    int wexcl = incl - run;
    if (lane == 31) wsum[w] = incl;
    __syncthreads();
    if (t == 0) {
        int a = 0;
#pragma unroll
        for (int i = 0; i < 8; i++) { int x = wsum[i]; wsum[i] = a; a += x; }
    }
    __syncthreads();
    int off = bsum[blockIdx.x] + wsum[w] + wexcl;
#pragma unroll
    for (int i = 0; i < 4; i++) {
        int idx = base + i;
        if (idx < n) {
            rowptr[idx + 1] = off + p[i];
            pos[idx]        = off + p[i] - v[i];
        }
    }
    if (blockIdx.x == 0 && t == 0) rowptr[0] = 0;
}

__global__ void scatter_kernel(const void* __restrict__ ei, int E, int n,
                               int* pos, int* colsrc) {
    int et = blockIdx.x * blockDim.x + threadIdx.x;
    int ET = E + n;
    if (et >= ET) return;
    int s, d;
    if (et < E) { s = loadIdx(ei, et); d = loadIdx(ei, (long long)E + et); }
    else        { s = d = et - E; }
    int p = atomicAdd(&pos[d], 1);
    colsrc[p] = s;
}

// ---------------------------------------------------------------------------
// cp.async tf32 GEMM with FUSED alpha + fp16 epilogue.
// hh[M,128] = fp16(A@W);  aS/aD[M,H] = per-head dots with attS/attD.
// ---------------------------------------------------------------------------
#define CP_ASYNC16(dst_smem_u32, src_ptr) \
    asm volatile("cp.async.ca.shared.global [%0], [%1], 16;\n" \
                 :: "r"(dst_smem_u32), "l"(src_ptr))
#define CP_COMMIT() asm volatile("cp.async.commit_group;\n")
#define CP_WAIT(N)  asm volatile("cp.async.wait_group %0;\n" :: "n"(N))

__device__ __forceinline__ unsigned f2tf(float x) {
    unsigned r;
    asm("cvt.rna.tf32.f32 %0, %1;" : "=r"(r) : "f"(x));
    return r;
}

__device__ __forceinline__ void mma_tf32(float* c, const unsigned* a,
                                         unsigned b0, unsigned b1) {
    asm volatile(
        "mma.sync.aligned.m16n8k8.row.col.f32.tf32.tf32.f32 "
        "{%0,%1,%2,%3}, {%4,%5,%6,%7}, {%8,%9}, {%0,%1,%2,%3};"
        : "+f"(c[0]), "+f"(c[1]), "+f"(c[2]), "+f"(c[3])
        : "r"(a[0]), "r"(a[1]), "r"(a[2]), "r"(a[3]), "r"(b0), "r"(b1));
}

#define AS_STRIDE 36
#define BS_STRIDE 136
#define AS_ELEMS  (128 * AS_STRIDE)
#define BS_ELEMS  (32 * BS_STRIDE)
#define ATT_OFF   (2 * AS_ELEMS + 2 * BS_ELEMS)          // sAttS[128], sAttD[128]
#define GEMM_SMEM ((ATT_OFF + 256) * 4)

template <int H>
__global__ __launch_bounds__(256, 2)
void gemm128_fused(const float* __restrict__ A, const float* __restrict__ W,
                   const float* __restrict__ attS, const float* __restrict__ attD,
                   __half* __restrict__ hh, float* __restrict__ aS,
                   float* __restrict__ aD, int M)
{
    extern __shared__ float dsm[];
    float* AsBase = dsm;
    float* BsBase = dsm + 2 * AS_ELEMS;
    float* sAttS  = dsm + ATT_OFF;
    float* sAttD  = sAttS + 128;

    int t = threadIdx.x, lane = t & 31, wid = t >> 5;
    int wm = wid & 3, wn = wid >> 2;
    int rowBase = blockIdx.x * 128;

    // stage att vectors
    if (t < 128)       sAttS[t] = attS[t];
    else               sAttD[t - 128] = attD[t - 128];

    float acc[2][8][4];
#pragma unroll
    for (int mt = 0; mt < 2; mt++)
#pragma unroll
        for (int nt = 0; nt < 8; nt++)
#pragma unroll
            for (int i = 0; i < 4; i++) acc[mt][nt][i] = 0.f;

    auto loadChunk = [&](int k0, int buf) {
        float* As = AsBase + buf * AS_ELEMS;
        float* Bs = BsBase + buf * BS_ELEMS;
#pragma unroll
        for (int r = 0; r < 4; r++) {
            int id = t + r * 256;
            int arow = id >> 3;
            int cg   = (id & 7) * 4;
            int grow = rowBase + arow;
            float* dst = As + arow * AS_STRIDE + cg;
            if (grow < M) {
                unsigned sdst = (unsigned)__cvta_generic_to_shared(dst);
                CP_ASYNC16(sdst, A + (size_t)grow * 128 + k0 + cg);
            } else {
                *(float4*)dst = make_float4(0.f, 0.f, 0.f, 0.f);
            }
        }
#pragma unroll
        for (int r = 0; r < 4; r++) {
            int id = t + r * 256;
            int krow = id >> 5;
            int c4   = (id & 31) * 4;
            float* dst = Bs + krow * BS_STRIDE + c4;
            unsigned sdst = (unsigned)__cvta_generic_to_shared(dst);
            CP_ASYNC16(sdst, W + (size_t)(k0 + krow) * 128 + c4);
        }
        CP_COMMIT();
    };

    auto compute = [&](int buf) {
        const float* As = AsBase + buf * AS_ELEMS;
        const float* Bs = BsBase + buf * BS_ELEMS;
#pragma unroll
        for (int ks = 0; ks < 4; ks++) {
            int kk = ks * 8;
            unsigned a[2][4];
#pragma unroll
            for (int mt = 0; mt < 2; mt++) {
                int row = wm * 32 + mt * 16 + (lane >> 2);
                int kc  = kk + (lane & 3);
                a[mt][0] = f2tf(As[row * AS_STRIDE + kc]);
                a[mt][1] = f2tf(As[(row + 8) * AS_STRIDE + kc]);
                a[mt][2] = f2tf(As[row * AS_STRIDE + kc + 4]);
                a[mt][3] = f2tf(As[(row + 8) * AS_STRIDE + kc + 4]);
            }
#pragma unroll
            for (int nt = 0; nt < 8; nt++) {
                int col = wn * 64 + nt * 8 + (lane >> 2);
                int kc  = kk + (lane & 3);
                unsigned b0 = f2tf(Bs[kc * BS_STRIDE + col]);
                unsigned b1 = f2tf(Bs[(kc + 4) * BS_STRIDE + col]);
                mma_tf32(acc[0][nt], a[0], b0, b1);
                mma_tf32(acc[1][nt], a[1], b0, b1);
            }
        }
    };

    loadChunk(0, 0);
    loadChunk(32, 1);
    CP_WAIT(1);
    __syncthreads();
    compute(0);
    __syncthreads();
    loadChunk(64, 0);
    CP_WAIT(1);
    __syncthreads();
    compute(1);
    __syncthreads();
    loadChunk(96, 1);
    CP_WAIT(1);
    __syncthreads();
    compute(0);
    __syncthreads();
    CP_WAIT(0);
    __syncthreads();
    compute(1);

    // ---- epilogue: fp16 mirror stores ----
#pragma unroll
    for (int mt = 0; mt < 2; mt++) {
#pragma unroll
        for (int nt = 0; nt < 8; nt++) {
            int row = rowBase + wm * 32 + mt * 16 + (lane >> 2);
            int col = wn * 64 + nt * 8 + (lane & 3) * 2;
            if (row < M)
                *(__half2*)(hh + (size_t)row * 128 + col) =
                    __floats2half2_rn(acc[mt][nt][0], acc[mt][nt][1]);
            if (row + 8 < M)
                *(__half2*)(hh + (size_t)(row + 8) * 128 + col) =
                    __floats2half2_rn(acc[mt][nt][2], acc[mt][nt][3]);
        }
    }

    // ---- epilogue: fused alpha dots ----
    if (H == 4) {
        // warp wn covers heads 2wn (nt<4) and 2wn+1 (nt>=4); no cross-warp red.
#pragma unroll
        for (int mt = 0; mt < 2; mt++) {
#pragma unroll
            for (int rp = 0; rp < 2; rp++) {
                float ps0 = 0.f, pd0 = 0.f, ps1 = 0.f, pd1 = 0.f;
#pragma unroll
                for (int nt = 0; nt < 8; nt++) {
                    int col = wn * 64 + nt * 8 + (lane & 3) * 2;
                    float a0 = acc[mt][nt][2 * rp];
                    float a1 = acc[mt][nt][2 * rp + 1];
                    float s  = a0 * sAttS[col] + a1 * sAttS[col + 1];
                    float dd = a0 * sAttD[col] + a1 * sAttD[col + 1];
                    if (nt < 4) { ps0 += s; pd0 += dd; }
                    else        { ps1 += s; pd1 += dd; }
                }
#pragma unroll
                for (int o = 1; o < 4; o <<= 1) {
                    ps0 += __shfl_xor_sync(0xffffffffu, ps0, o);
                    pd0 += __shfl_xor_sync(0xffffffffu, pd0, o);
                    ps1 += __shfl_xor_sync(0xffffffffu, ps1, o);
                    pd1 += __shfl_xor_sync(0xffffffffu, pd1, o);
                }
                if ((lane & 3) == 0) {
                    int row = rowBase + wm * 32 + mt * 16 + rp * 8 + (lane >> 2);
                    if (row < M) {
                        aS[(size_t)row * 4 + 2 * wn]     = ps0;
                        aD[(size_t)row * 4 + 2 * wn]     = pd0;
                        aS[(size_t)row * 4 + 2 * wn + 1] = ps1;
                        aD[(size_t)row * 4 + 2 * wn + 1] = pd1;
                    }
                }
            }
        }
    } else {
        // H == 1: cross-warp (wn) reduction via smem (reuse As region)
        __syncthreads();                 // smem free after last compute
        float* sRedS = AsBase;           // [128][2]
        float* sRedD = AsBase + 256;     // [128][2]
#pragma unroll
        for (int mt = 0; mt < 2; mt++) {
#pragma unroll
            for (int rp = 0; rp < 2; rp++) {
                float ps = 0.f, pd = 0.f;
#pragma unroll
                for (int nt = 0; nt < 8; nt++) {
                    int col = wn * 64 + nt * 8 + (lane & 3) * 2;
                    float a0 = acc[mt][nt][2 * rp];
                    float a1 = acc[mt][nt][2 * rp + 1];
                    ps += a0 * sAttS[col] + a1 * sAttS[col + 1];
                    pd += a0 * sAttD[col] + a1 * sAttD[col + 1];
                }
#pragma unroll
                for (int o = 1; o < 4; o <<= 1) {
                    ps += __shfl_xor_sync(0xffffffffu, ps, o);
                    pd += __shfl_xor_sync(0xffffffffu, pd, o);
                }
                if ((lane & 3) == 0) {
                    int lrow = wm * 32 + mt * 16 + rp * 8 + (lane >> 2);
                    sRedS[lrow * 2 + wn] = ps;
                    sRedD[lrow * 2 + wn] = pd;
                }
            }
        }
        __syncthreads();
        if (t < 128) {
            int row = rowBase + t;
            if (row < M) {
                aS[row] = sRedS[t * 2] + sRedS[t * 2 + 1];
                aD[row] = sRedD[t * 2] + sRedD[t * 2 + 1];
            }
        }
    }
}

// ---------------------------------------------------------------------------
// SINGLE-PASS warp-per-node softmax aggregation.
// RELU=true : out = relu(acc/den + bias)  (layer1, feeds gemm2)
// RELU=false: out = acc/den + bias        (layer2 final)
// ---------------------------------------------------------------------------
template <int H, bool RELU>
__global__ void node_agg_kernel(const int* __restrict__ rowptr,
                                const int* __restrict__ colsrc,
                                const float* __restrict__ aS,
                                const float* __restrict__ aD,
                                const __half* __restrict__ hh,
                                const float* __restrict__ bias,
                                float* __restrict__ out, int n)
{
    int d    = (int)((blockIdx.x * (size_t)blockDim.x + threadIdx.x) >> 5);
    int lane = threadIdx.x & 31;
    if (d >= n) return;
    int beg = rowptr[d], end = rowptr[d + 1];

    const int OC = 128 / H;
    int hd = (lane * 4) / OC;
    float aDh = aD[(size_t)d * H + hd];

    float den = 0.f;
    float4 acc = make_float4(0.f, 0.f, 0.f, 0.f);
    for (int base = beg; base < end; base += 32) {
        int cnt = min(32, end - base);
        int idx = base + lane;
        int sv  = (idx < end) ? colsrc[idx] : 0;
#pragma unroll 4
        for (int j = 0; j < cnt; j++) {
            int sidx = __shfl_sync(0xffffffffu, sv, j);
            float e = aS[(size_t)sidx * H + hd] + aDh;
            e = e > 0.f ? e : 0.2f * e;
            float wgt = __expf(e);
            den += wgt;
            uint2 u = *(const uint2*)(hh + (size_t)sidx * 128 + lane * 4);
            float2 v0 = __half22float2(*(__half2*)&u.x);
            float2 v1 = __half22float2(*(__half2*)&u.y);
            acc.x += wgt * v0.x;
            acc.y += wgt * v0.y;
            acc.z += wgt * v1.x;
            acc.w += wgt * v1.y;
        }
    }
    float inv = 1.f / fmaxf(den, 1e-38f);
    float4 b = *(const float4*)(bias + lane * 4);
    acc.x = acc.x * inv + b.x;
    acc.y = acc.y * inv + b.y;
    acc.z = acc.z * inv + b.z;
    acc.w = acc.w * inv + b.w;
    if (RELU) {
        acc.x = fmaxf(acc.x, 0.f);
        acc.y = fmaxf(acc.y, 0.f);
        acc.z = fmaxf(acc.z, 0.f);
        acc.w = fmaxf(acc.w, 0.f);
    }
    *(float4*)(out + (size_t)d * 128 + lane * 4) = acc;
}

// ---------------------------------------------------------------------------
// host
// ---------------------------------------------------------------------------
extern "C" void kernel_launch(void* const* d_in, const int* in_sizes, int n_in,
                              void* d_out, int out_size)
{
    const float* x   = (const float*)d_in[0];
    const void*  ei  = d_in[1];
    const float* W1  = (const float*)d_in[2];
    const float* as1 = (const float*)d_in[3];
    const float* ad1 = (const float*)d_in[4];
    const float* b1  = (const float*)d_in[5];
    const float* W2  = (const float*)d_in[6];
    const float* as2 = (const float*)d_in[7];
    const float* ad2 = (const float*)d_in[8];
    const float* b2  = (const float*)d_in[9];
    float* out = (float*)d_out;

    int n  = in_sizes[0] / 128;
    int E  = in_sizes[1] / 2;
    int ET = E + n;

    float *agg, *aS, *aD;
    __half *hh;
    int *deg, *rowptr, *pos, *colsrc, *bsum;
    cudaGetSymbolAddress((void**)&hh,     g_hh);
    cudaGetSymbolAddress((void**)&agg,    g_agg);
    cudaGetSymbolAddress((void**)&aS,     g_aS);
    cudaGetSymbolAddress((void**)&aD,     g_aD);
    cudaGetSymbolAddress((void**)&deg,    g_deg);
    cudaGetSymbolAddress((void**)&rowptr, g_rowptr);
    cudaGetSymbolAddress((void**)&pos,    g_pos);
    cudaGetSymbolAddress((void**)&colsrc, g_colsrc);
    cudaGetSymbolAddress((void**)&bsum,   g_bsum);

    static bool inited = false;
    if (!inited) {
        cudaFuncSetAttribute(gemm128_fused<4>,
                             cudaFuncAttributeMaxDynamicSharedMemorySize,
                             GEMM_SMEM);
        cudaFuncSetAttribute(gemm128_fused<1>,
                             cudaFuncAttributeMaxDynamicSharedMemorySize,
                             GEMM_SMEM);
        inited = true;
    }

    const int TB = 256;
    int gridGemm  = (n + 127) / 128;
    int gridEdge  = (ET + TB - 1) / TB;
    int gridNodeW = (n + 7) / 8;
    int nScanBlk  = (n + 1023) / 1024;

    // CSR build interleaved with gemm1 (single stream; gemm1 is 4th launch)
    detect_kernel<<<1, 32>>>((const int*)ei);
    zero_int<<<(n + TB - 1) / TB, TB>>>(deg, n);
    hist_kernel<<<gridEdge, TB>>>(ei, E, n, deg);
    gemm128_fused<4><<<gridGemm, TB, GEMM_SMEM>>>(x, W1, as1, ad1,
                                                  hh, aS, aD, n);
    block_sum_kernel<<<nScanBlk, 256>>>(deg, bsum, n);
    scan_bsum_kernel<<<1, 32>>>(bsum, nScanBlk);
    scan_final_kernel<<<nScanBlk, 256>>>(deg, bsum, rowptr, pos, n);
    scatter_kernel<<<gridEdge, TB>>>(ei, E, n, pos, colsrc);

    // ----- layer 1 aggregation (H=4): relu(.+b1) -----
    node_agg_kernel<4, true><<<gridNodeW, TB>>>(rowptr, colsrc, aS, aD, hh,
                                                b1, agg, n);

    // ----- layer 2 (H=1): gemm+alpha fused, agg applies (.+b2) -----
    gemm128_fused<1><<<gridGemm, TB, GEMM_SMEM>>>(agg, W2, as2, ad2,
                                                  hh, aS, aD, n);
    node_agg_kernel<1, false><<<gridNodeW, TB>>>(rowptr, colsrc, aS, aD, hh,
                                                 b2, out, n);
}

// round 16
// speedup vs baseline: 1.5465x; 1.0489x over previous
#include <cuda_runtime.h>
#include <cuda_fp16.h>
#include <math.h>

// ---------------------------------------------------------------------------
// GAT 2-layer: N=50000 nodes, E=800000 edges (+N self loops), F=128.
// Layer1: heads=4, out_ch=32.  Layer2: heads=1, out_ch=128.
// CSR-by-dst built once; SINGLE-PASS warp softmax-aggregation; fp16 HMMA
// GEMM (m16n8k16, fp32 accum) with FUSED alpha + fp16-mirror epilogue.
// ---------------------------------------------------------------------------

#define NMAX   50048
#define ETMAX  (800000 + NMAX)

__device__ __half g_hh[(size_t)NMAX * 128];    // fp16 h (gather + mirror)
__device__ __half g_xh[(size_t)NMAX * 128];    // fp16 copy of x
__device__ __half g_aggh[(size_t)NMAX * 128];  // fp16 layer1 output
__device__ __half g_wt1[128 * 128];            // W1^T fp16 [n][k]
__device__ __half g_wt2[128 * 128];            // W2^T fp16 [n][k]
__device__ float  g_aS[NMAX * 4];
__device__ float  g_aD[NMAX * 4];
__device__ int    g_deg[NMAX];
__device__ int    g_rowptr[NMAX + 1];
__device__ int    g_pos[NMAX];
__device__ int    g_colsrc[ETMAX];
__device__ int    g_bsum[64];
__device__ int    g_is64;

// ---------------------------------------------------------------------------
__device__ __forceinline__ int loadIdx(const void* ei, long long pos) {
    if (g_is64) return (int)((const long long*)ei)[pos];
    return ((const int*)ei)[pos];
}

__global__ void detect_kernel(const int* ei) {
    int lane = threadIdx.x;
    int hi = ei[2 * lane + 1];
    unsigned z = __ballot_sync(0xffffffffu, hi == 0);
    if (lane == 0) g_is64 = (__popc(z) >= 30) ? 1 : 0;
}

__global__ void zero_int(int* p, int count) {
    int i = blockIdx.x * blockDim.x + threadIdx.x;
    if (i < count) p[i] = 0;
}

// fp32 -> fp16 bulk convert (count divisible by 4)
__global__ void convert_fp16(const float* __restrict__ src,
                             __half* __restrict__ dst, int count4) {
    int i = blockIdx.x * blockDim.x + threadIdx.x;
    if (i >= count4) return;
    float4 v = *(const float4*)(src + (size_t)i * 4);
    __half2 p0 = __floats2half2_rn(v.x, v.y);
    __half2 p1 = __floats2half2_rn(v.z, v.w);
    *(uint2*)(dst + (size_t)i * 4) =
        make_uint2(*(unsigned*)&p0, *(unsigned*)&p1);
}

// W[128k][128n] fp32 -> Wt[128n][128k] fp16
__global__ void transpose_w(const float* __restrict__ W, __half* __restrict__ Wt) {
    int i = blockIdx.x * blockDim.x + threadIdx.x;   // 16384
    int k = i >> 7, n = i & 127;
    Wt[n * 128 + k] = __float2half(W[k * 128 + n]);
}

__global__ void hist_kernel(const void* __restrict__ ei, int E, int n, int* deg) {
    int et = blockIdx.x * blockDim.x + threadIdx.x;
    int ET = E + n;
    if (et >= ET) return;
    int d = (et < E) ? loadIdx(ei, (long long)E + et) : et - E;
    atomicAdd(&deg[d], 1);
}

// ---- 3-phase scan --------------------------------------------------------
__global__ void block_sum_kernel(const int* __restrict__ deg, int* bsum, int n) {
    __shared__ int wsum[8];
    int t = threadIdx.x, lane = t & 31, w = t >> 5;
    int base = blockIdx.x * 1024 + t * 4;
    int v = 0;
#pragma unroll
    for (int i = 0; i < 4; i++)
        if (base + i < n) v += deg[base + i];
#pragma unroll
    for (int o = 16; o; o >>= 1) v += __shfl_xor_sync(0xffffffffu, v, o);
    if (lane == 0) wsum[w] = v;
    __syncthreads();
    if (t == 0) {
        int s = 0;
#pragma unroll
        for (int i = 0; i < 8; i++) s += wsum[i];
        bsum[blockIdx.x] = s;
    }
}

__global__ void scan_bsum_kernel(int* bsum, int nb) {
    int lane = threadIdx.x;
    int carry = 0;
    for (int base = 0; base < nb; base += 32) {
        int i = base + lane;
        int v = (i < nb) ? bsum[i] : 0;
        int incl = v;
#pragma unroll
        for (int o = 1; o < 32; o <<= 1) {
            int x = __shfl_up_sync(0xffffffffu, incl, o);
            if (lane >= o) incl += x;
        }
        if (i < nb) bsum[i] = carry + incl - v;
        carry += __shfl_sync(0xffffffffu, incl, 31);
    }
}

__global__ void scan_final_kernel(const int* __restrict__ deg,
                                  const int* __restrict__ bsum,
                                  int* rowptr, int* pos, int n) {
    __shared__ int wsum[8];
    int t = threadIdx.x, lane = t & 31, w = t >> 5;
    int base = blockIdx.x * 1024 + t * 4;
    int v[4], p[4];
    int run = 0;
#pragma unroll
    for (int i = 0; i < 4; i++) {
        v[i] = (base + i < n) ? deg[base + i] : 0;
        run += v[i];
        p[i] = run;
    }
    int incl = run;
#pragma unroll
    for (int o = 1; o < 32; o <<= 1) {
        int x = __shfl_up_sync(0xffffffffu, incl, o);
        if (lane >= o) incl += x;
    }
    int wexcl = incl - run;
    if (lane == 31) wsum[w] = incl;
    __syncthreads();
    if (t == 0) {
        int a = 0;
#pragma unroll
        for (int i = 0; i < 8; i++) { int x = wsum[i]; wsum[i] = a; a += x; }
    }
    __syncthreads();
    int off = bsum[blockIdx.x] + wsum[w] + wexcl;
#pragma unroll
    for (int i = 0; i < 4; i++) {
        int idx = base + i;
        if (idx < n) {
            rowptr[idx + 1] = off + p[i];
            pos[idx]        = off + p[i] - v[i];
        }
    }
    if (blockIdx.x == 0 && t == 0) rowptr[0] = 0;
}

__global__ void scatter_kernel(const void* __restrict__ ei, int E, int n,
                               int* pos, int* colsrc) {
    int et = blockIdx.x * blockDim.x + threadIdx.x;
    int ET = E + n;
    if (et >= ET) return;
    int s, d;
    if (et < E) { s = loadIdx(ei, et); d = loadIdx(ei, (long long)E + et); }
    else        { s = d = et - E; }
    int p = atomicAdd(&pos[d], 1);
    colsrc[p] = s;
}

// ---------------------------------------------------------------------------
// fp16 HMMA GEMM (m16n8k16) with FUSED alpha + fp16 epilogue.
// A: fp16 [M][128]; Wt: fp16 [128n][128k]; hh = fp16(A@W); aS/aD per-head dots.
// ---------------------------------------------------------------------------
#define CP_ASYNC16(dst_smem_u32, src_ptr) \
    asm volatile("cp.async.ca.shared.global [%0], [%1], 16;\n" \
                 :: "r"(dst_smem_u32), "l"(src_ptr))
#define CP_COMMIT() asm volatile("cp.async.commit_group;\n")
#define CP_WAIT(N)  asm volatile("cp.async.wait_group %0;\n" :: "n"(N))

__device__ __forceinline__ void mma_fp16(float* c, const unsigned* a,
                                         unsigned b0, unsigned b1) {
    asm volatile(
        "mma.sync.aligned.m16n8k16.row.col.f32.f16.f16.f32 "
        "{%0,%1,%2,%3}, {%4,%5,%6,%7}, {%8,%9}, {%0,%1,%2,%3};"
        : "+f"(c[0]), "+f"(c[1]), "+f"(c[2]), "+f"(c[3])
        : "r"(a[0]), "r"(a[1]), "r"(a[2]), "r"(a[3]), "r"(b0), "r"(b1));
}

#define TILE_STRIDE 40                         // halves; 80B = 20 banks
#define TILE_H_ELEMS (128 * TILE_STRIDE)       // per buffer (A or Bt)
#define SM_BYTES  (4 * TILE_H_ELEMS * 2)       // 2 bufs x (A + Bt)
#define GEMM_SMEM (SM_BYTES + 256 * 4)         // + sAttS/sAttD

template <int H>
__global__ __launch_bounds__(256, 2)
void gemm128_h(const __half* __restrict__ A, const __half* __restrict__ Wt,
               const float* __restrict__ attS, const float* __restrict__ attD,
               __half* __restrict__ hh, float* __restrict__ aS,
               float* __restrict__ aD, int M)
{
    extern __shared__ char dsm[];
    __half* AsBase = (__half*)dsm;                       // [2][128][40]
    __half* BtBase = AsBase + 2 * TILE_H_ELEMS;          // [2][128][40]
    float*  sAttS  = (float*)(dsm + SM_BYTES);
    float*  sAttD  = sAttS + 128;

    int t = threadIdx.x, lane = t & 31, wid = t >> 5;
    int wm = wid & 3, wn = wid >> 2;
    int rowBase = blockIdx.x * 128;

    if (t < 128)       sAttS[t] = attS[t];
    else               sAttD[t - 128] = attD[t - 128];

    float acc[2][8][4];
#pragma unroll
    for (int mt = 0; mt < 2; mt++)
#pragma unroll
        for (int nt = 0; nt < 8; nt++)
#pragma unroll
            for (int i = 0; i < 4; i++) acc[mt][nt][i] = 0.f;

    auto loadChunk = [&](int k0, int buf) {
        __half* As = AsBase + buf * TILE_H_ELEMS;
        __half* Bt = BtBase + buf * TILE_H_ELEMS;
#pragma unroll
        for (int r = 0; r < 2; r++) {
            int id = t + r * 256;                // 512 ids: row=id>>2, seg=(id&3)*8
            int row = id >> 2;
            int sg  = (id & 3) * 8;
            int grow = rowBase + row;
            __half* dA = As + row * TILE_STRIDE + sg;
            if (grow < M) {
                unsigned sdst = (unsigned)__cvta_generic_to_shared(dA);
                CP_ASYNC16(sdst, A + (size_t)grow * 128 + k0 + sg);
            } else {
                *(uint4*)dA = make_uint4(0, 0, 0, 0);
            }
            __half* dB = Bt + row * TILE_STRIDE + sg;    // row == col index
            unsigned sdstB = (unsigned)__cvta_generic_to_shared(dB);
            CP_ASYNC16(sdstB, Wt + (size_t)row * 128 + k0 + sg);
        }
        CP_COMMIT();
    };

    auto compute = [&](int buf) {
        const __half* As = AsBase + buf * TILE_H_ELEMS;
        const __half* Bt = BtBase + buf * TILE_H_ELEMS;
#pragma unroll
        for (int ks = 0; ks < 2; ks++) {
            int kb = ks * 16 + (lane & 3) * 2;
            unsigned a[2][4];
#pragma unroll
            for (int mt = 0; mt < 2; mt++) {
                int row = wm * 32 + mt * 16 + (lane >> 2);
                a[mt][0] = *(const unsigned*)(As + row * TILE_STRIDE + kb);
                a[mt][1] = *(const unsigned*)(As + (row + 8) * TILE_STRIDE + kb);
                a[mt][2] = *(const unsigned*)(As + row * TILE_STRIDE + kb + 8);
                a[mt][3] = *(const unsigned*)(As + (row + 8) * TILE_STRIDE + kb + 8);
            }
#pragma unroll
            for (int nt = 0; nt < 8; nt++) {
                int col = wn * 64 + nt * 8 + (lane >> 2);
                unsigned b0 = *(const unsigned*)(Bt + col * TILE_STRIDE + kb);
                unsigned b1 = *(const unsigned*)(Bt + col * TILE_STRIDE + kb + 8);
                mma_fp16(acc[0][nt], a[0], b0, b1);
                mma_fp16(acc[1][nt], a[1], b0, b1);
            }
        }
    };

    loadChunk(0, 0);
    loadChunk(32, 1);
    CP_WAIT(1);
    __syncthreads();
    compute(0);
    __syncthreads();
    loadChunk(64, 0);
    CP_WAIT(1);
    __syncthreads();
    compute(1);
    __syncthreads();
    loadChunk(96, 1);
    CP_WAIT(1);
    __syncthreads();
    compute(0);
    __syncthreads();
    CP_WAIT(0);
    __syncthreads();
    compute(1);

    // ---- epilogue: fp16 h stores ----
#pragma unroll
    for (int mt = 0; mt < 2; mt++) {
#pragma unroll
        for (int nt = 0; nt < 8; nt++) {
            int row = rowBase + wm * 32 + mt * 16 + (lane >> 2);
            int col = wn * 64 + nt * 8 + (lane & 3) * 2;
            if (row < M)
                *(__half2*)(hh + (size_t)row * 128 + col) =
                    __floats2half2_rn(acc[mt][nt][0], acc[mt][nt][1]);
            if (row + 8 < M)
                *(__half2*)(hh + (size_t)(row + 8) * 128 + col) =
                    __floats2half2_rn(acc[mt][nt][2], acc[mt][nt][3]);
        }
    }

    // ---- epilogue: fused alpha dots ----
    if (H == 4) {
#pragma unroll
        for (int mt = 0; mt < 2; mt++) {
#pragma unroll
            for (int rp = 0; rp < 2; rp++) {
                float ps0 = 0.f, pd0 = 0.f, ps1 = 0.f, pd1 = 0.f;
#pragma unroll
                for (int nt = 0; nt < 8; nt++) {
                    int col = wn * 64 + nt * 8 + (lane & 3) * 2;
                    float a0 = acc[mt][nt][2 * rp];
                    float a1 = acc[mt][nt][2 * rp + 1];
                    float s  = a0 * sAttS[col] + a1 * sAttS[col + 1];
                    float dd = a0 * sAttD[col] + a1 * sAttD[col + 1];
                    if (nt < 4) { ps0 += s; pd0 += dd; }
                    else        { ps1 += s; pd1 += dd; }
                }
#pragma unroll
                for (int o = 1; o < 4; o <<= 1) {
                    ps0 += __shfl_xor_sync(0xffffffffu, ps0, o);
                    pd0 += __shfl_xor_sync(0xffffffffu, pd0, o);
                    ps1 += __shfl_xor_sync(0xffffffffu, ps1, o);
                    pd1 += __shfl_xor_sync(0xffffffffu, pd1, o);
                }
                if ((lane & 3) == 0) {
                    int row = rowBase + wm * 32 + mt * 16 + rp * 8 + (lane >> 2);
                    if (row < M) {
                        aS[(size_t)row * 4 + 2 * wn]     = ps0;
                        aD[(size_t)row * 4 + 2 * wn]     = pd0;
                        aS[(size_t)row * 4 + 2 * wn + 1] = ps1;
                        aD[(size_t)row * 4 + 2 * wn + 1] = pd1;
                    }
                }
            }
        }
    } else {
        __syncthreads();
        float* sRedS = (float*)dsm;          // reuse tile smem
        float* sRedD = sRedS + 256;
#pragma unroll
        for (int mt = 0; mt < 2; mt++) {
#pragma unroll
            for (int rp = 0; rp < 2; rp++) {
                float ps = 0.f, pd = 0.f;
#pragma unroll
                for (int nt = 0; nt < 8; nt++) {
                    int col = wn * 64 + nt * 8 + (lane & 3) * 2;
                    float a0 = acc[mt][nt][2 * rp];
                    float a1 = acc[mt][nt][2 * rp + 1];
                    ps += a0 * sAttS[col] + a1 * sAttS[col + 1];
                    pd += a0 * sAttD[col] + a1 * sAttD[col + 1];
                }
#pragma unroll
                for (int o = 1; o < 4; o <<= 1) {
                    ps += __shfl_xor_sync(0xffffffffu, ps, o);
                    pd += __shfl_xor_sync(0xffffffffu, pd, o);
                }
                if ((lane & 3) == 0) {
                    int lrow = wm * 32 + mt * 16 + rp * 8 + (lane >> 2);
                    sRedS[lrow * 2 + wn] = ps;
                    sRedD[lrow * 2 + wn] = pd;
                }
            }
        }
        __syncthreads();
        if (t < 128) {
            int row = rowBase + t;
            if (row < M) {
                aS[row] = sRedS[t * 2] + sRedS[t * 2 + 1];
                aD[row] = sRedD[t * 2] + sRedD[t * 2 + 1];
            }
        }
    }
}

// ---------------------------------------------------------------------------
// SINGLE-PASS warp-per-node softmax aggregation.
// OUT_HALF=true : out = fp16(relu(acc/den + bias))  (layer1, feeds gemm2)
// OUT_HALF=false: out = acc/den + bias (fp32)       (layer2 final)
// ---------------------------------------------------------------------------
template <int H, bool OUT_HALF>
__global__ void node_agg_kernel(const int* __restrict__ rowptr,
                                const int* __restrict__ colsrc,
                                const float* __restrict__ aS,
                                const float* __restrict__ aD,
                                const __half* __restrict__ hh,
                                const float* __restrict__ bias,
                                void* __restrict__ outv, int n)
{
    int d    = (int)((blockIdx.x * (size_t)blockDim.x + threadIdx.x) >> 5);
    int lane = threadIdx.x & 31;
    if (d >= n) return;
    int beg = rowptr[d], end = rowptr[d + 1];

    const int OC = 128 / H;
    int hd = (lane * 4) / OC;
    float aDh = aD[(size_t)d * H + hd];

    float den = 0.f;
    float4 acc = make_float4(0.f, 0.f, 0.f, 0.f);
    for (int base = beg; base < end; base += 32) {
        int cnt = min(32, end - base);
        int idx = base + lane;
        int sv  = (idx < end) ? colsrc[idx] : 0;
#pragma unroll 4
        for (int j = 0; j < cnt; j++) {
            int sidx = __shfl_sync(0xffffffffu, sv, j);
            float e = aS[(size_t)sidx * H + hd] + aDh;
            e = e > 0.f ? e : 0.2f * e;
            float wgt = __expf(e);
            den += wgt;
            uint2 u = *(const uint2*)(hh + (size_t)sidx * 128 + lane * 4);
            float2 v0 = __half22float2(*(__half2*)&u.x);
            float2 v1 = __half22float2(*(__half2*)&u.y);
            acc.x += wgt * v0.x;
            acc.y += wgt * v0.y;
            acc.z += wgt * v1.x;
            acc.w += wgt * v1.y;
        }
    }
    float inv = 1.f / fmaxf(den, 1e-38f);
    float4 b = *(const float4*)(bias + lane * 4);
    acc.x = acc.x * inv + b.x;
    acc.y = acc.y * inv + b.y;
    acc.z = acc.z * inv + b.z;
    acc.w = acc.w * inv + b.w;
    if (OUT_HALF) {
        acc.x = fmaxf(acc.x, 0.f);
        acc.y = fmaxf(acc.y, 0.f);
        acc.z = fmaxf(acc.z, 0.f);
        acc.w = fmaxf(acc.w, 0.f);
        __half2 p0 = __floats2half2_rn(acc.x, acc.y);
        __half2 p1 = __floats2half2_rn(acc.z, acc.w);
        *(uint2*)((__half*)outv + (size_t)d * 128 + lane * 4) =
            make_uint2(*(unsigned*)&p0, *(unsigned*)&p1);
    } else {
        *(float4*)((float*)outv + (size_t)d * 128 + lane * 4) = acc;
    }
}

// ---------------------------------------------------------------------------
// host
// ---------------------------------------------------------------------------
extern "C" void kernel_launch(void* const* d_in, const int* in_sizes, int n_in,
                              void* d_out, int out_size)
{
    const float* x   = (const float*)d_in[0];
    const void*  ei  = d_in[1];
    const float* W1  = (const float*)d_in[2];
    const float* as1 = (const float*)d_in[3];
    const float* ad1 = (const float*)d_in[4];
    const float* b1  = (const float*)d_in[5];
    const float* W2  = (const float*)d_in[6];
    const float* as2 = (const float*)d_in[7];
    const float* ad2 = (const float*)d_in[8];
    const float* b2  = (const float*)d_in[9];
    float* out = (float*)d_out;

    int n  = in_sizes[0] / 128;
    int E  = in_sizes[1] / 2;
    int ET = E + n;

    float *aS, *aD;
    __half *hh, *xh, *aggh, *wt1, *wt2;
    int *deg, *rowptr, *pos, *colsrc, *bsum;
    cudaGetSymbolAddress((void**)&hh,     g_hh);
    cudaGetSymbolAddress((void**)&xh,     g_xh);
    cudaGetSymbolAddress((void**)&aggh,   g_aggh);
    cudaGetSymbolAddress((void**)&wt1,    g_wt1);
    cudaGetSymbolAddress((void**)&wt2,    g_wt2);
    cudaGetSymbolAddress((void**)&aS,     g_aS);
    cudaGetSymbolAddress((void**)&aD,     g_aD);
    cudaGetSymbolAddress((void**)&deg,    g_deg);
    cudaGetSymbolAddress((void**)&rowptr, g_rowptr);
    cudaGetSymbolAddress((void**)&pos,    g_pos);
    cudaGetSymbolAddress((void**)&colsrc, g_colsrc);
    cudaGetSymbolAddress((void**)&bsum,   g_bsum);

    static bool inited = false;
    if (!inited) {
        cudaFuncSetAttribute(gemm128_h<4>,
                             cudaFuncAttributeMaxDynamicSharedMemorySize,
                             GEMM_SMEM);
        cudaFuncSetAttribute(gemm128_h<1>,
                             cudaFuncAttributeMaxDynamicSharedMemorySize,
                             GEMM_SMEM);
        inited = true;
    }

    const int TB = 256;
    int gridGemm  = (n + 127) / 128;
    int gridEdge  = (ET + TB - 1) / TB;
    int gridNodeW = (n + 7) / 8;
    int nScanBlk  = (n + 1023) / 1024;
    int nConv4    = n * 32;   // n*128/4

    // prep: fp16 conversions + W transposes + CSR build, gemm1 interleaved
    detect_kernel<<<1, 32>>>((const int*)ei);
    convert_fp16<<<(nConv4 + TB - 1) / TB, TB>>>(x, xh, nConv4);
    transpose_w<<<64, 256>>>(W1, wt1);
    transpose_w<<<64, 256>>>(W2, wt2);
    zero_int<<<(n + TB - 1) / TB, TB>>>(deg, n);
    hist_kernel<<<gridEdge, TB>>>(ei, E, n, deg);
    gemm128_h<4><<<gridGemm, TB, GEMM_SMEM>>>(xh, wt1, as1, ad1,
                                              hh, aS, aD, n);
    block_sum_kernel<<<nScanBlk, 256>>>(deg, bsum, n);
    scan_bsum_kernel<<<1, 32>>>(bsum, nScanBlk);
    scan_final_kernel<<<nScanBlk, 256>>>(deg, bsum, rowptr, pos, n);
    scatter_kernel<<<gridEdge, TB>>>(ei, E, n, pos, colsrc);

    // ----- layer 1 aggregation (H=4): fp16(relu(.+b1)) -----
    node_agg_kernel<4, true><<<gridNodeW, TB>>>(rowptr, colsrc, aS, aD, hh,
                                                b1, aggh, n);

    // ----- layer 2 (H=1): fp16 gemm+alpha fused, agg applies (.+b2) -----
    gemm128_h<1><<<gridGemm, TB, GEMM_SMEM>>>(aggh, wt2, as2, ad2,
                                              hh, aS, aD, n);
    node_agg_kernel<1, false><<<gridNodeW, TB>>>(rowptr, colsrc, aS, aD, hh,
                                                 b2, out, n);
}

// round 17
// speedup vs baseline: 1.6132x; 1.0431x over previous
#include <cuda_runtime.h>
#include <cuda_fp16.h>
#include <math.h>

// ---------------------------------------------------------------------------
// GAT 2-layer: N=50000 nodes, E=800000 edges (+N self loops), F=128.
// Layer1: heads=4, out_ch=32.  Layer2: heads=1, out_ch=128.
// CSR-by-dst built once; SINGLE-PASS warp softmax-aggregation; fp16 HMMA
// GEMM (m16n8k16, fp32 accum) with FUSED alpha + fp16-mirror epilogue.
// All prep (detect, x->fp16, W transposes, deg zero) fused into ONE kernel.
// ---------------------------------------------------------------------------

#define NMAX   50048
#define ETMAX  (800000 + NMAX)

__device__ __half g_hh[(size_t)NMAX * 128];    // fp16 h (gather + mirror)
__device__ __half g_xh[(size_t)NMAX * 128];    // fp16 copy of x
__device__ __half g_aggh[(size_t)NMAX * 128];  // fp16 layer1 output
__device__ __half g_wt1[128 * 128];            // W1^T fp16 [n][k]
__device__ __half g_wt2[128 * 128];            // W2^T fp16 [n][k]
__device__ float  g_aS[NMAX * 4];
__device__ float  g_aD[NMAX * 4];
__device__ int    g_deg[NMAX];
__device__ int    g_rowptr[NMAX + 1];
__device__ int    g_pos[NMAX];
__device__ int    g_colsrc[ETMAX];
__device__ int    g_bsum[64];
__device__ int    g_is64;

// ---------------------------------------------------------------------------
__device__ __forceinline__ int loadIdx(const void* ei, long long pos) {
    if (g_is64) return (int)((const long long*)ei)[pos];
    return ((const int*)ei)[pos];
}

// ---------------------------------------------------------------------------
// fused prep: blocks [0,64)=W1^T, [64,128)=W2^T (+detect in block 0),
// [128,128+nZero)=deg zero, rest = x -> fp16 convert.
// ---------------------------------------------------------------------------
__global__ void prep_kernel(const int* __restrict__ ei,
                            const float* __restrict__ x, __half* __restrict__ xh,
                            const float* __restrict__ W1,
                            const float* __restrict__ W2,
                            __half* __restrict__ wt1, __half* __restrict__ wt2,
                            int* __restrict__ deg, int n, int nZero)
{
    int b = blockIdx.x, t = threadIdx.x;
    if (b < 64) {
        if (b == 0 && t < 32) {
            int hi = ei[2 * t + 1];
            unsigned z = __ballot_sync(0xffffffffu, hi == 0);
            if (t == 0) g_is64 = (__popc(z) >= 30) ? 1 : 0;
        }
        int i = b * 256 + t;
        int k = i >> 7, c = i & 127;
        wt1[c * 128 + k] = __float2half(W1[k * 128 + c]);
    } else if (b < 128) {
        int i = (b - 64) * 256 + t;
        int k = i >> 7, c = i & 127;
        wt2[c * 128 + k] = __float2half(W2[k * 128 + c]);
    } else if (b < 128 + nZero) {
        int i = (b - 128) * 256 + t;
        if (i < n) deg[i] = 0;
    } else {
        int i = (b - 128 - nZero) * 256 + t;     // float4 index
        if (i < n * 32) {
            float4 v = *(const float4*)(x + (size_t)i * 4);
            __half2 p0 = __floats2half2_rn(v.x, v.y);
            __half2 p1 = __floats2half2_rn(v.z, v.w);
            *(uint2*)(xh + (size_t)i * 4) =
                make_uint2(*(unsigned*)&p0, *(unsigned*)&p1);
        }
    }
}

__global__ void hist_kernel(const void* __restrict__ ei, int E, int n, int* deg) {
    int et = blockIdx.x * blockDim.x + threadIdx.x;
    int ET = E + n;
    if (et >= ET) return;
    int d = (et < E) ? loadIdx(ei, (long long)E + et) : et - E;
    atomicAdd(&deg[d], 1);
}

// ---- 3-phase scan --------------------------------------------------------
__global__ void block_sum_kernel(const int* __restrict__ deg, int* bsum, int n) {
    __shared__ int wsum[8];
    int t = threadIdx.x, lane = t & 31, w = t >> 5;
    int base = blockIdx.x * 1024 + t * 4;
    int v = 0;
#pragma unroll
    for (int i = 0; i < 4; i++)
        if (base + i < n) v += deg[base + i];
#pragma unroll
    for (int o = 16; o; o >>= 1) v += __shfl_xor_sync(0xffffffffu, v, o);
    if (lane == 0) wsum[w] = v;
    __syncthreads();
    if (t == 0) {
        int s = 0;
#pragma unroll
        for (int i = 0; i < 8; i++) s += wsum[i];
        bsum[blockIdx.x] = s;
    }
}

__global__ void scan_bsum_kernel(int* bsum, int nb) {
    int lane = threadIdx.x;
    int carry = 0;
    for (int base = 0; base < nb; base += 32) {
        int i = base + lane;
        int v = (i < nb) ? bsum[i] : 0;
        int incl = v;
#pragma unroll
        for (int o = 1; o < 32; o <<= 1) {
            int x = __shfl_up_sync(0xffffffffu, incl, o);
            if (lane >= o) incl += x;
        }
        if (i < nb) bsum[i] = carry + incl - v;
        carry += __shfl_sync(0xffffffffu, incl, 31);
    }
}

__global__ void scan_final_kernel(const int* __restrict__ deg,
                                  const int* __restrict__ bsum,
                                  int* rowptr, int* pos, int n) {
    __shared__ int wsum[8];
    int t = threadIdx.x, lane = t & 31, w = t >> 5;
    int base = blockIdx.x * 1024 + t * 4;
    int v[4], p[4];
    int run = 0;
#pragma unroll
    for (int i = 0; i < 4; i++) {
        v[i] = (base + i < n) ? deg[base + i] : 0;
        run += v[i];
        p[i] = run;
    }
    int incl = run;
#pragma unroll
    for (int o = 1; o < 32; o <<= 1) {
        int x = __shfl_up_sync(0xffffffffu, incl, o);
        if (lane >= o) incl += x;
    }
    int wexcl = incl - run;
    if (lane == 31) wsum[w] = incl;
    __syncthreads();
    if (t == 0) {
        int a = 0;
#pragma unroll
        for (int i = 0; i < 8; i++) { int x = wsum[i]; wsum[i] = a; a += x; }
    }
    __syncthreads();
    int off = bsum[blockIdx.x] + wsum[w] + wexcl;
#pragma unroll
    for (int i = 0; i < 4; i++) {
        int idx = base + i;
        if (idx < n) {
            rowptr[idx + 1] = off + p[i];
            pos[idx]        = off + p[i] - v[i];
        }
    }
    if (blockIdx.x == 0 && t == 0) rowptr[0] = 0;
}

__global__ void scatter_kernel(const void* __restrict__ ei, int E, int n,
                               int* pos, int* colsrc) {
    int et = blockIdx.x * blockDim.x + threadIdx.x;
    int ET = E + n;
    if (et >= ET) return;
    int s, d;
    if (et < E) { s = loadIdx(ei, et); d = loadIdx(ei, (long long)E + et); }
    else        { s = d = et - E; }
    int p = atomicAdd(&pos[d], 1);
    colsrc[p] = s;
}

// ---------------------------------------------------------------------------
// fp16 HMMA GEMM (m16n8k16) with FUSED alpha + fp16 epilogue.
// ---------------------------------------------------------------------------
#define CP_ASYNC16(dst_smem_u32, src_ptr) \
    asm volatile("cp.async.ca.shared.global [%0], [%1], 16;\n" \
                 :: "r"(dst_smem_u32), "l"(src_ptr))
#define CP_COMMIT() asm volatile("cp.async.commit_group;\n")
#define CP_WAIT(N)  asm volatile("cp.async.wait_group %0;\n" :: "n"(N))

__device__ __forceinline__ void mma_fp16(float* c, const unsigned* a,
                                         unsigned b0, unsigned b1) {
    asm volatile(
        "mma.sync.aligned.m16n8k16.row.col.f32.f16.f16.f32 "
        "{%0,%1,%2,%3}, {%4,%5,%6,%7}, {%8,%9}, {%0,%1,%2,%3};"
        : "+f"(c[0]), "+f"(c[1]), "+f"(c[2]), "+f"(c[3])
        : "r"(a[0]), "r"(a[1]), "r"(a[2]), "r"(a[3]), "r"(b0), "r"(b1));
}

#define TILE_STRIDE 40
#define TILE_H_ELEMS (128 * TILE_STRIDE)
#define SM_BYTES  (4 * TILE_H_ELEMS * 2)
#define GEMM_SMEM (SM_BYTES + 256 * 4)

template <int H>
__global__ __launch_bounds__(256, 2)
void gemm128_h(const __half* __restrict__ A, const __half* __restrict__ Wt,
               const float* __restrict__ attS, const float* __restrict__ attD,
               __half* __restrict__ hh, float* __restrict__ aS,
               float* __restrict__ aD, int M)
{
    extern __shared__ char dsm[];
    __half* AsBase = (__half*)dsm;
    __half* BtBase = AsBase + 2 * TILE_H_ELEMS;
    float*  sAttS  = (float*)(dsm + SM_BYTES);
    float*  sAttD  = sAttS + 128;

    int t = threadIdx.x, lane = t & 31, wid = t >> 5;
    int wm = wid & 3, wn = wid >> 2;
    int rowBase = blockIdx.x * 128;

    if (t < 128)       sAttS[t] = attS[t];
    else               sAttD[t - 128] = attD[t - 128];

    float acc[2][8][4];
#pragma unroll
    for (int mt = 0; mt < 2; mt++)
#pragma unroll
        for (int nt = 0; nt < 8; nt++)
#pragma unroll
            for (int i = 0; i < 4; i++) acc[mt][nt][i] = 0.f;

    auto loadChunk = [&](int k0, int buf) {
        __half* As = AsBase + buf * TILE_H_ELEMS;
        __half* Bt = BtBase + buf * TILE_H_ELEMS;
#pragma unroll
        for (int r = 0; r < 2; r++) {
            int id = t + r * 256;
            int row = id >> 2;
            int sg  = (id & 3) * 8;
            int grow = rowBase + row;
            __half* dA = As + row * TILE_STRIDE + sg;
            if (grow < M) {
                unsigned sdst = (unsigned)__cvta_generic_to_shared(dA);
                CP_ASYNC16(sdst, A + (size_t)grow * 128 + k0 + sg);
            } else {
                *(uint4*)dA = make_uint4(0, 0, 0, 0);
            }
            __half* dB = Bt + row * TILE_STRIDE + sg;
            unsigned sdstB = (unsigned)__cvta_generic_to_shared(dB);
            CP_ASYNC16(sdstB, Wt + (size_t)row * 128 + k0 + sg);
        }
        CP_COMMIT();
    };

    auto compute = [&](int buf) {
        const __half* As = AsBase + buf * TILE_H_ELEMS;
        const __half* Bt = BtBase + buf * TILE_H_ELEMS;
#pragma unroll
        for (int ks = 0; ks < 2; ks++) {
            int kb = ks * 16 + (lane & 3) * 2;
            unsigned a[2][4];
#pragma unroll
            for (int mt = 0; mt < 2; mt++) {
                int row = wm * 32 + mt * 16 + (lane >> 2);
                a[mt][0] = *(const unsigned*)(As + row * TILE_STRIDE + kb);
                a[mt][1] = *(const unsigned*)(As + (row + 8) * TILE_STRIDE + kb);
                a[mt][2] = *(const unsigned*)(As + row * TILE_STRIDE + kb + 8);
                a[mt][3] = *(const unsigned*)(As + (row + 8) * TILE_STRIDE + kb + 8);
            }
#pragma unroll
            for (int nt = 0; nt < 8; nt++) {
                int col = wn * 64 + nt * 8 + (lane >> 2);
                unsigned b0 = *(const unsigned*)(Bt + col * TILE_STRIDE + kb);
                unsigned b1 = *(const unsigned*)(Bt + col * TILE_STRIDE + kb + 8);
                mma_fp16(acc[0][nt], a[0], b0, b1);
                mma_fp16(acc[1][nt], a[1], b0, b1);
            }
        }
    };

    loadChunk(0, 0);
    loadChunk(32, 1);
    CP_WAIT(1);
    __syncthreads();
    compute(0);
    __syncthreads();
    loadChunk(64, 0);
    CP_WAIT(1);
    __syncthreads();
    compute(1);
    __syncthreads();
    loadChunk(96, 1);
    CP_WAIT(1);
    __syncthreads();
    compute(0);
    __syncthreads();
    CP_WAIT(0);
    __syncthreads();
    compute(1);

    // ---- epilogue: fp16 h stores ----
#pragma unroll
    for (int mt = 0; mt < 2; mt++) {
#pragma unroll
        for (int nt = 0; nt < 8; nt++) {
            int row = rowBase + wm * 32 + mt * 16 + (lane >> 2);
            int col = wn * 64 + nt * 8 + (lane & 3) * 2;
            if (row < M)
                *(__half2*)(hh + (size_t)row * 128 + col) =
                    __floats2half2_rn(acc[mt][nt][0], acc[mt][nt][1]);
            if (row + 8 < M)
                *(__half2*)(hh + (size_t)(row + 8) * 128 + col) =
                    __floats2half2_rn(acc[mt][nt][2], acc[mt][nt][3]);
        }
    }

    // ---- epilogue: fused alpha dots ----
    if (H == 4) {
#pragma unroll
        for (int mt = 0; mt < 2; mt++) {
#pragma unroll
            for (int rp = 0; rp < 2; rp++) {
                float ps0 = 0.f, pd0 = 0.f, ps1 = 0.f, pd1 = 0.f;
#pragma unroll
                for (int nt = 0; nt < 8; nt++) {
                    int col = wn * 64 + nt * 8 + (lane & 3) * 2;
                    float a0 = acc[mt][nt][2 * rp];
                    float a1 = acc[mt][nt][2 * rp + 1];
                    float s  = a0 * sAttS[col] + a1 * sAttS[col + 1];
                    float dd = a0 * sAttD[col] + a1 * sAttD[col + 1];
                    if (nt < 4) { ps0 += s; pd0 += dd; }
                    else        { ps1 += s; pd1 += dd; }
                }
#pragma unroll
                for (int o = 1; o < 4; o <<= 1) {
                    ps0 += __shfl_xor_sync(0xffffffffu, ps0, o);
                    pd0 += __shfl_xor_sync(0xffffffffu, pd0, o);
                    ps1 += __shfl_xor_sync(0xffffffffu, ps1, o);
                    pd1 += __shfl_xor_sync(0xffffffffu, pd1, o);
                }
                if ((lane & 3) == 0) {
                    int row = rowBase + wm * 32 + mt * 16 + rp * 8 + (lane >> 2);
                    if (row < M) {
                        aS[(size_t)row * 4 + 2 * wn]     = ps0;
                        aD[(size_t)row * 4 + 2 * wn]     = pd0;
                        aS[(size_t)row * 4 + 2 * wn + 1] = ps1;
                        aD[(size_t)row * 4 + 2 * wn + 1] = pd1;
                    }
                }
            }
        }
    } else {
        __syncthreads();
        float* sRedS = (float*)dsm;
        float* sRedD = sRedS + 256;
#pragma unroll
        for (int mt = 0; mt < 2; mt++) {
#pragma unroll
            for (int rp = 0; rp < 2; rp++) {
                float ps = 0.f, pd = 0.f;
#pragma unroll
                for (int nt = 0; nt < 8; nt++) {
                    int col = wn * 64 + nt * 8 + (lane & 3) * 2;
                    float a0 = acc[mt][nt][2 * rp];
                    float a1 = acc[mt][nt][2 * rp + 1];
                    ps += a0 * sAttS[col] + a1 * sAttS[col + 1];
                    pd += a0 * sAttD[col] + a1 * sAttD[col + 1];
                }
#pragma unroll
                for (int o = 1; o < 4; o <<= 1) {
                    ps += __shfl_xor_sync(0xffffffffu, ps, o);
                    pd += __shfl_xor_sync(0xffffffffu, pd, o);
                }
                if ((lane & 3) == 0) {
                    int lrow = wm * 32 + mt * 16 + rp * 8 + (lane >> 2);
                    sRedS[lrow * 2 + wn] = ps;
                    sRedD[lrow * 2 + wn] = pd;
                }
            }
        }
        __syncthreads();
        if (t < 128) {
            int row = rowBase + t;
            if (row < M) {
                aS[row] = sRedS[t * 2] + sRedS[t * 2 + 1];
                aD[row] = sRedD[t * 2] + sRedD[t * 2 + 1];
            }
        }
    }
}

// ---------------------------------------------------------------------------
// SINGLE-PASS warp-per-node softmax aggregation.
// ---------------------------------------------------------------------------
template <int H, bool OUT_HALF>
__global__ void node_agg_kernel(const int* __restrict__ rowptr,
                                const int* __restrict__ colsrc,
                                const float* __restrict__ aS,
                                const float* __restrict__ aD,
                                const __half* __restrict__ hh,
                                const float* __restrict__ bias,
                                void* __restrict__ outv, int n)
{
    int d    = (int)((blockIdx.x * (size_t)blockDim.x + threadIdx.x) >> 5);
    int lane = threadIdx.x & 31;
    if (d >= n) return;
    int beg = rowptr[d], end = rowptr[d + 1];

    const int OC = 128 / H;
    int hd = (lane * 4) / OC;
    float aDh = aD[(size_t)d * H + hd];

    float den = 0.f;
    float4 acc = make_float4(0.f, 0.f, 0.f, 0.f);
    for (int base = beg; base < end; base += 32) {
        int cnt = min(32, end - base);
        int idx = base + lane;
        int sv  = (idx < end) ? colsrc[idx] : 0;
#pragma unroll 4
        for (int j = 0; j < cnt; j++) {
            int sidx = __shfl_sync(0xffffffffu, sv, j);
            float e = aS[(size_t)sidx * H + hd] + aDh;
            e = e > 0.f ? e : 0.2f * e;
            float wgt = __expf(e);
            den += wgt;
            uint2 u = *(const uint2*)(hh + (size_t)sidx * 128 + lane * 4);
            float2 v0 = __half22float2(*(__half2*)&u.x);
            float2 v1 = __half22float2(*(__half2*)&u.y);
            acc.x += wgt * v0.x;
            acc.y += wgt * v0.y;
            acc.z += wgt * v1.x;
            acc.w += wgt * v1.y;
        }
    }
    float inv = 1.f / fmaxf(den, 1e-38f);
    float4 b = *(const float4*)(bias + lane * 4);
    acc.x = acc.x * inv + b.x;
    acc.y = acc.y * inv + b.y;
    acc.z = acc.z * inv + b.z;
    acc.w = acc.w * inv + b.w;
    if (OUT_HALF) {
        acc.x = fmaxf(acc.x, 0.f);
        acc.y = fmaxf(acc.y, 0.f);
        acc.z = fmaxf(acc.z, 0.f);
        acc.w = fmaxf(acc.w, 0.f);
        __half2 p0 = __floats2half2_rn(acc.x, acc.y);
        __half2 p1 = __floats2half2_rn(acc.z, acc.w);
        *(uint2*)((__half*)outv + (size_t)d * 128 + lane * 4) =
            make_uint2(*(unsigned*)&p0, *(unsigned*)&p1);
    } else {
        *(float4*)((float*)outv + (size_t)d * 128 + lane * 4) = acc;
    }
}

// ---------------------------------------------------------------------------
// host
// ---------------------------------------------------------------------------
extern "C" void kernel_launch(void* const* d_in, const int* in_sizes, int n_in,
                              void* d_out, int out_size)
{
    const float* x   = (const float*)d_in[0];
    const void*  ei  = d_in[1];
    const float* W1  = (const float*)d_in[2];
    const float* as1 = (const float*)d_in[3];
    const float* ad1 = (const float*)d_in[4];
    const float* b1  = (const float*)d_in[5];
    const float* W2  = (const float*)d_in[6];
    const float* as2 = (const float*)d_in[7];
    const float* ad2 = (const float*)d_in[8];
    const float* b2  = (const float*)d_in[9];
    float* out = (float*)d_out;

    int n  = in_sizes[0] / 128;
    int E  = in_sizes[1] / 2;
    int ET = E + n;

    float *aS, *aD;
    __half *hh, *xh, *aggh, *wt1, *wt2;
    int *deg, *rowptr, *pos, *colsrc, *bsum;
    cudaGetSymbolAddress((void**)&hh,     g_hh);
    cudaGetSymbolAddress((void**)&xh,     g_xh);
    cudaGetSymbolAddress((void**)&aggh,   g_aggh);
    cudaGetSymbolAddress((void**)&wt1,    g_wt1);
    cudaGetSymbolAddress((void**)&wt2,    g_wt2);
    cudaGetSymbolAddress((void**)&aS,     g_aS);
    cudaGetSymbolAddress((void**)&aD,     g_aD);
    cudaGetSymbolAddress((void**)&deg,    g_deg);
    cudaGetSymbolAddress((void**)&rowptr, g_rowptr);
    cudaGetSymbolAddress((void**)&pos,    g_pos);
    cudaGetSymbolAddress((void**)&colsrc, g_colsrc);
    cudaGetSymbolAddress((void**)&bsum,   g_bsum);

    static bool inited = false;
    if (!inited) {
        cudaFuncSetAttribute(gemm128_h<4>,
                             cudaFuncAttributeMaxDynamicSharedMemorySize,
                             GEMM_SMEM);
        cudaFuncSetAttribute(gemm128_h<1>,
                             cudaFuncAttributeMaxDynamicSharedMemorySize,
                             GEMM_SMEM);
        inited = true;
    }

    const int TB = 256;
    int gridGemm  = (n + 127) / 128;
    int gridEdge  = (ET + TB - 1) / TB;
    int gridNodeW = (n + 7) / 8;
    int nScanBlk  = (n + 1023) / 1024;
    int nZero     = (n + TB - 1) / TB;
    int nConvBlk  = (n * 32 + TB - 1) / TB;
    int gridPrep  = 128 + nZero + nConvBlk;

    // fused prep (detect + W transposes + deg zero + x->fp16)
    prep_kernel<<<gridPrep, TB>>>((const int*)ei, x, xh, W1, W2,
                                  wt1, wt2, deg, n, nZero);
    hist_kernel<<<gridEdge, TB>>>(ei, E, n, deg);
    gemm128_h<4><<<gridGemm, TB, GEMM_SMEM>>>(xh, wt1, as1, ad1,
                                              hh, aS, aD, n);
    block_sum_kernel<<<nScanBlk, 256>>>(deg, bsum, n);
    scan_bsum_kernel<<<1, 32>>>(bsum, nScanBlk);
    scan_final_kernel<<<nScanBlk, 256>>>(deg, bsum, rowptr, pos, n);
    scatter_kernel<<<gridEdge, TB>>>(ei, E, n, pos, colsrc);

    // ----- layer 1 aggregation (H=4): fp16(relu(.+b1)) -----
    node_agg_kernel<4, true><<<gridNodeW, TB>>>(rowptr, colsrc, aS, aD, hh,
                                                b1, aggh, n);

    // ----- layer 2 (H=1): fp16 gemm+alpha fused, agg applies (.+b2) -----
    gemm128_h<1><<<gridGemm, TB, GEMM_SMEM>>>(aggh, wt2, as2, ad2,
                                              hh, aS, aD, n);
    node_agg_kernel<1, false><<<gridNodeW, TB>>>(rowptr, colsrc, aS, aD, hh,
                                                 b2, out, n);
}